// round 13
// baseline (speedup 1.0000x reference)
#include <cuda_runtime.h>
#include <cuda_fp16.h>
#include <math.h>

// ---------------- scratch (device globals; no allocations) ----------------
__device__ float g_X[33554432];
__device__ float g_O[33554432];
__device__ float g_feat[512 * 256];
__device__ float g_gi[512 * 384];
__device__ float g_hid[512 * 128];
__device__ float g_fcwT[256 * 8192];     // reused as fp16 slot8-grouped fc weights
__device__ __half2 g_wperm2[49152];

__device__ __forceinline__ float sigf(float x) { return 1.0f / (1.0f + expf(-x)); }

__device__ __forceinline__ unsigned tf32u(float x) {
    unsigned r;
    asm("cvt.rna.tf32.f32 %0, %1;" : "=r"(r) : "f"(x));
    return r;
}
__device__ __forceinline__ float tf32f(float x) { return __uint_as_float(tf32u(x)); }

__device__ __forceinline__ void mma8(float* c, unsigned a0, unsigned a1, unsigned a2, unsigned a3,
                                     float b0f, float b1f) {
    unsigned b0 = __float_as_uint(b0f), b1 = __float_as_uint(b1f);
    asm volatile(
        "mma.sync.aligned.m16n8k8.row.col.f32.tf32.tf32.f32 "
        "{%0,%1,%2,%3},{%4,%5,%6,%7},{%8,%9},{%0,%1,%2,%3};"
        : "+f"(c[0]), "+f"(c[1]), "+f"(c[2]), "+f"(c[3])
        : "r"(a0), "r"(a1), "r"(a2), "r"(a3), "r"(b0), "r"(b1));
}
__device__ __forceinline__ void mma16h(float* c, unsigned a0, unsigned a1, unsigned a2, unsigned a3,
                                       unsigned b0, unsigned b1) {
    asm volatile(
        "mma.sync.aligned.m16n8k16.row.col.f32.f16.f16.f32 "
        "{%0,%1,%2,%3},{%4,%5,%6,%7},{%8,%9},{%0,%1,%2,%3};"
        : "+f"(c[0]), "+f"(c[1]), "+f"(c[2]), "+f"(c[3])
        : "r"(a0), "r"(a1), "r"(a2), "r"(a3), "r"(b0), "r"(b1));
}
__device__ __forceinline__ void mma8h(float* c, unsigned a0, unsigned a1, unsigned b0) {
    asm volatile(
        "mma.sync.aligned.m16n8k8.row.col.f32.f16.f16.f32 "
        "{%0,%1,%2,%3},{%4,%5},{%6},{%0,%1,%2,%3};"
        : "+f"(c[0]), "+f"(c[1]), "+f"(c[2]), "+f"(c[3])
        : "r"(a0), "r"(a1), "r"(b0));
}
__device__ __forceinline__ void ldsm_x4(unsigned& r0, unsigned& r1, unsigned& r2, unsigned& r3,
                                        unsigned addr) {
    asm volatile("ldmatrix.sync.aligned.m8n8.x4.shared.b16 {%0,%1,%2,%3}, [%4];"
                 : "=r"(r0), "=r"(r1), "=r"(r2), "=r"(r3) : "r"(addr));
}
__device__ __forceinline__ void ldsm_x2(unsigned& r0, unsigned& r1, unsigned addr) {
    asm volatile("ldmatrix.sync.aligned.m8n8.x2.shared.b16 {%0,%1}, [%2];"
                 : "=r"(r0), "=r"(r1) : "r"(addr));
}
#define U(x) __float_as_uint(x)

__device__ __forceinline__ int pslot(int p, int PAIRS) {
    if (PAIRS == 4)  return p;
    if (PAIRS == 8)  return 2 * (p & 3) + (p >> 2);
    return 4 * (p & 3) + (p >> 2);
}
__device__ __forceinline__ unsigned packh2(float a, float b) {
    __half2 h = __floats2half2_rn(a, b);
    return *(unsigned*)&h;
}
__device__ __forceinline__ unsigned relu_u(unsigned u) {
    __half2 h = *(__half2*)&u;
    h = __hmax2(h, __half2half2(__float2half(0.0f)));
    return *(unsigned*)&h;
}
__device__ __forceinline__ uint4 relu4(uint4 v) {
    v.x = relu_u(v.x); v.y = relu_u(v.y); v.z = relu_u(v.z); v.w = relu_u(v.w);
    return v;
}

// ---------------- weight permute prepass -> fp16 pairs [tap][co][pslot] ----
__global__ void wperm_all_kernel(const float* __restrict__ s0c, const float* __restrict__ s0r,
                                 const float* __restrict__ s1c, const float* __restrict__ s1r,
                                 const float* __restrict__ s2c, const float* __restrict__ s2r,
                                 __half2* __restrict__ dst) {
    int i = blockIdx.x * 256 + threadIdx.x;
    if (i >= 48960) return;
    const float* src; int CIN, PAIRS, COUT, base;
    if (i < 576)        { src = s0c; CIN = 6;  PAIRS = 4;  COUT = 16; base = 0; }
    else if (i < 5184)  { src = s0r; CIN = 16; PAIRS = 8;  COUT = 16; base = 576; }
    else if (i < 7488)  { src = s1c; CIN = 16; PAIRS = 8;  COUT = 32; base = 5184; }
    else if (i < 25920) { src = s1r; CIN = 32; PAIRS = 16; COUT = 32; base = 7488; }
    else if (i < 30528) { src = s2c; CIN = 32; PAIRS = 16; COUT = 32; base = 25920; }
    else                { src = s2r; CIN = 32; PAIRS = 16; COUT = 32; base = 30528; }
    int li = i - base;
    int tap = li % 9; int r = li / 9;
    int p = r % PAIRS; r /= PAIRS;
    int co = r % COUT; int cv = r / COUT;
    int ci0 = 2 * p, ci1 = 2 * p + 1;
    float v0 = (ci0 < CIN) ? src[((cv * COUT + co) * CIN + ci0) * 9 + tap] : 0.0f;
    float v1 = (ci1 < CIN) ? src[((cv * COUT + co) * CIN + ci1) * 9 + tap] : 0.0f;
    dst[base + cv * 9 * COUT * PAIRS + (tap * COUT + co) * PAIRS + pslot(p, PAIRS)] =
        __floats2half2_rn(v0, v1);
}

// fc_w -> fp16 slot8-grouped pairs: k = c*256+p; pairidx = k/2; group=pairidx>>3
__global__ void fcwh_permute(const float* __restrict__ w, __half2* __restrict__ wt) {
    int i = blockIdx.x * 256 + threadIdx.x;   // i = n*4096 + pairidx
    if (i >= 256 * 4096) return;
    int n = i >> 12, pairidx = i & 4095;
    int g = pairidx >> 3, q = pairidx & 7;
    int k = 2 * pairidx;
    wt[(long)n * 4096 + g * 8 + pslot(q, 8)] =
        __floats2half2_rn(w[(long)n * 8192 + k], w[(long)n * 8192 + k + 1]);
}

// ---------------- fused conv kernel (TW = tile width, height 16) -----------
// MODE 0: conv -> maxpool -> fp16 out.  MODE 1: resblock fp16 out.  MODE 2: fp32 NHWC out.
template <int TW, int CIN, int COUT, bool RELU_IN, int MODE, bool RELU_OUT, bool NCHW>
__global__ __launch_bounds__(256, 4) void conv_fused_kernel(
    const void* __restrict__ in, const __half2* __restrict__ w1,
    const float* __restrict__ b1v, const __half2* __restrict__ w2,
    const float* __restrict__ b2v, void* __restrict__ out,
    const void* __restrict__ resid, int H, int W) {
    constexpr int CINP = (CIN <= 8) ? 8 : ((CIN <= 16) ? 16 : 32);
    constexpr int PAIRS = CINP / 2;
    constexpr int POP = COUT / 2;
    constexpr int NB = COUT / 8;
    constexpr int HW = TW + 4;          // halo width, 20 rows tall
    constexpr int RW = TW + 2;          // conv1 region width, 18 rows tall
    constexpr int HPIX = 20 * HW;
    constexpr int NPIX = 18 * RW;
    constexpr int NSUB = (NPIX + 127) / 128;
    constexpr int ISTR = (PAIRS == 4) ? 4 : ((PAIRS == 8) ? 12 : 16);
    constexpr int IN_W = HPIX * ISTR;
    constexpr int MSTR = (MODE == 0) ? POP : ((POP == 8) ? 12 : 16);
    constexpr int MID_W = NPIX * MSTR;

    extern __shared__ __half2 smh[];
    __half2* s_in2 = smh;
    __half2* s_mid2 = smh + IN_W;

    const int tid = threadIdx.x;
    const int n = blockIdx.z;
    const int by = blockIdx.y * 16, bx = blockIdx.x * TW;
    const unsigned sb_in = (unsigned)__cvta_generic_to_shared(s_in2);
    const unsigned sb_mid = (unsigned)__cvta_generic_to_shared(s_mid2);

    for (int i = tid; i < MID_W; i += 256) ((unsigned*)s_mid2)[i] = 0u;

    // ---- stage halo (20 x HW) ----
    for (int p = tid; p < HPIX; p += 256) {
        int iy = p / HW, ix = p - iy * HW;
        int gy = by + iy - 2, gx = bx + ix - 2;
        bool ok = (gy >= 0 && gy < H && gx >= 0 && gx < W);
        if (NCHW) {
            const float* inf = (const float*)in;
            uint4 wv = make_uint4(0u, 0u, 0u, 0u);
            if (ok) {
                long base = ((long)n * CIN * H + gy) * W + gx;
                long st = (long)H * W;
                wv = make_uint4(packh2(inf[base], inf[base + st]),
                                packh2(inf[base + 2 * st], inf[base + 3 * st]),
                                packh2(inf[base + 4 * st], inf[base + 5 * st]), 0u);
            }
            *(uint4*)(s_in2 + p * 4) = wv;
        } else if (PAIRS == 8) {
            uint4 lo = make_uint4(0u, 0u, 0u, 0u), hi = lo;
            if (ok) {
                const uint4* gp = (const uint4*)((const __half2*)in + ((long)(n * H + gy) * W + gx) * 8);
                lo = gp[0]; hi = gp[1];
                if (RELU_IN) { lo = relu4(lo); hi = relu4(hi); }
            }
            *(uint4*)(s_in2 + p * 12) = lo;
            *(uint4*)(s_in2 + p * 12 + 4) = hi;
        } else {
            uint4 v0 = make_uint4(0,0,0,0), v1 = v0, v2 = v0, v3 = v0;
            if (ok) {
                const uint4* gp = (const uint4*)((const __half2*)in + ((long)(n * H + gy) * W + gx) * 16);
                v0 = gp[0]; v1 = gp[1]; v2 = gp[2]; v3 = gp[3];
                if (RELU_IN) { v0 = relu4(v0); v1 = relu4(v1); v2 = relu4(v2); v3 = relu4(v3); }
            }
            *(uint4*)(s_in2 + p * 16) = v0;
            *(uint4*)(s_in2 + p * 16 + 4) = v1;
            *(uint4*)(s_in2 + p * 16 + 8) = v2;
            *(uint4*)(s_in2 + p * 16 + 12) = v3;
        }
    }
    __syncthreads();

    const int warp = tid >> 5, lane = tid & 31, g = lane >> 2, t = lane & 3;
    const char* suc = (const char*)s_in2;
    const char* w1c = (const char*)w1;

    float acc1[NSUB][NB][4];
#pragma unroll
    for (int s = 0; s < NSUB; s++)
#pragma unroll
        for (int nb = 0; nb < NB; nb++)
#pragma unroll
            for (int q = 0; q < 4; q++) acc1[s][nb][q] = 0.0f;

    unsigned lmaddr[NSUB];
    const char* a0p[NSUB]; const char* a1p[NSUB];
    if (PAIRS == 4 || PAIRS == 8) {
        int i8 = lane & 7, mm = lane >> 3;
#pragma unroll
        for (int s = 0; s < NSUB; s++) {
            int tt = warp + 8 * s;
            int p = tt * 16 + i8 + (mm & 1) * 8;
            if (p > NPIX - 1) p = NPIX - 1;
            int pix = (p / RW + 1) * HW + (p % RW) + 1;
            if (PAIRS == 4) lmaddr[s] = sb_in + pix * 16;
            else            lmaddr[s] = sb_in + pix * 48 + (mm >> 1) * 16;
        }
    } else {
#pragma unroll
        for (int s = 0; s < NSUB; s++) {
            int tt = warp + 8 * s;
            int p0 = tt * 16 + g, p1 = p0 + 8;
            int q0 = p0 > NPIX - 1 ? NPIX - 1 : p0, q1 = p1 > NPIX - 1 ? NPIX - 1 : p1;
            int b0 = (q0 / RW + 1) * HW + (q0 % RW + 1);
            int b1 = (q1 / RW + 1) * HW + (q1 % RW + 1);
            a0p[s] = suc + b0 * 64 + t * 16;
            a1p[s] = suc + b1 * 64 + t * 16;
        }
    }
    const char* wp1[NB];
#pragma unroll
    for (int nb = 0; nb < NB; nb++) {
        int co = nb * 8 + g;
        if (PAIRS == 4)      wp1[nb] = w1c + co * 16 + t * 4;
        else if (PAIRS == 8) wp1[nb] = w1c + co * 32 + t * 8;
        else                 wp1[nb] = w1c + co * 64 + t * 16;
    }

#pragma unroll
    for (int tap = 0; tap < 9; tap++) {
        const int dy = tap / 3 - 1, dx = tap % 3 - 1;
        const int off = dy * HW + dx;
        if (PAIRS == 4) {
            const int wimm = tap * COUT * 16;
            unsigned vb[NB];
#pragma unroll
            for (int nb = 0; nb < NB; nb++) vb[nb] = *(const unsigned*)(wp1[nb] + wimm);
#pragma unroll
            for (int s = 0; s < NSUB; s++) {
                unsigned a0, a1;
                ldsm_x2(a0, a1, lmaddr[s] + off * 16);
#pragma unroll
                for (int nb = 0; nb < NB; nb++) mma8h(acc1[s][nb], a0, a1, vb[nb]);
            }
        } else if (PAIRS == 8) {
            const int wimm = tap * COUT * 32;
            uint2 vb[NB];
#pragma unroll
            for (int nb = 0; nb < NB; nb++) vb[nb] = *(const uint2*)(wp1[nb] + wimm);
#pragma unroll
            for (int s = 0; s < NSUB; s++) {
                unsigned a0, a1, a2, a3;
                ldsm_x4(a0, a1, a2, a3, lmaddr[s] + off * 48);
#pragma unroll
                for (int nb = 0; nb < NB; nb++)
                    mma16h(acc1[s][nb], a0, a1, a2, a3, vb[nb].x, vb[nb].y);
            }
        } else {
            const int wimm = tap * COUT * 64, aimm = off * 64;
            uint4 vb[NB];
#pragma unroll
            for (int nb = 0; nb < NB; nb++) vb[nb] = *(const uint4*)(wp1[nb] + wimm);
#pragma unroll
            for (int s = 0; s < NSUB; s++) {
                uint4 va0 = *(const uint4*)(a0p[s] + aimm);
                uint4 va1 = *(const uint4*)(a1p[s] + aimm);
#pragma unroll
                for (int nb = 0; nb < NB; nb++) {
                    mma16h(acc1[s][nb], va0.x, va1.x, va0.y, va1.y, vb[nb].x, vb[nb].y);
                    mma16h(acc1[s][nb], va0.z, va1.z, va0.w, va1.w, vb[nb].z, vb[nb].w);
                }
            }
        }
    }

    // ---- store conv1 results to mid ----
#pragma unroll
    for (int s = 0; s < NSUB; s++) {
        int pbase = (warp + 8 * s) * 16 + g;
#pragma unroll
        for (int half = 0; half < 2; half++) {
            int p = pbase + 8 * half;
            if (p < NPIX) {
                int r = p / RW, c = p - r * RW;
                int gy = by - 1 + r, gx = bx - 1 + c;
                if (gy >= 0 && gy < H && gx >= 0 && gx < W) {
#pragma unroll
                    for (int nb = 0; nb < NB; nb++) {
                        int co = nb * 8 + 2 * t;
                        int pr = nb * 4 + t;
                        float v0 = acc1[s][nb][2 * half + 0] + b1v[co];
                        float v1 = acc1[s][nb][2 * half + 1] + b1v[co + 1];
                        if (MODE == 0) {
                            s_mid2[p * POP + pr] = __floats2half2_rn(v0, v1);
                        } else if (POP == 8) {
                            s_mid2[p * 12 + pr] =
                                __floats2half2_rn(fmaxf(v0, 0.0f), fmaxf(v1, 0.0f));
                        } else {
                            s_mid2[p * 16 + (pslot(pr, 16) ^ ((p & 1) << 3))] =
                                __floats2half2_rn(fmaxf(v0, 0.0f), fmaxf(v1, 0.0f));
                        }
                    }
                }
            }
        }
    }
    __syncthreads();

    if (MODE == 0) {
        int H2 = H >> 1, W2 = W >> 1;
        __half2* outh = (__half2*)out;
        for (int o = tid; o < 4 * TW * POP; o += 256) {
            int pr = o % POP; int pp = o / POP;
            int ly = pp / (TW / 2), lx = pp % (TW / 2);
            __half2 m = __floats2half2_rn(-65504.0f, -65504.0f);
#pragma unroll
            for (int dy = 0; dy < 3; dy++) {
                int r = 2 * ly + dy;
                int gy = by - 1 + r;
                if (gy < 0 || gy >= H) continue;
#pragma unroll
                for (int dxx = 0; dxx < 3; dxx++) {
                    int c = 2 * lx + dxx;
                    int gx = bx - 1 + c;
                    if (gx < 0 || gx >= W) continue;
                    m = __hmax2(m, s_mid2[(r * RW + c) * POP + pr]);
                }
            }
            long op = ((long)n * H2 + (by / 2 + ly)) * W2 + (bx / 2 + lx);
            outh[op * POP + (COUT == 16 ? pr : pslot(pr, 16))] = m;
        }
    } else {
        const char* muc = (const char*)s_mid2;
        const char* w2c = (const char*)w2;
        const int wr0 = warp * 2;
        float acc[2][NB][4];
#pragma unroll
        for (int r = 0; r < 2; r++)
#pragma unroll
            for (int nb = 0; nb < NB; nb++)
#pragma unroll
                for (int q = 0; q < 4; q++) acc[r][nb][q] = 0.0f;

        unsigned m_lm[2];
        if (POP == 8) {
            int i8 = lane & 7, mm = lane >> 3;
#pragma unroll
            for (int r = 0; r < 2; r++) {
                int pix = (wr0 + r + 1) * RW + 1 + i8 + (mm & 1) * 8;
                m_lm[r] = sb_mid + pix * 48 + (mm >> 1) * 16;
            }
        }
        const char* wp2[NB];
#pragma unroll
        for (int nb = 0; nb < NB; nb++) {
            int co = nb * 8 + g;
            wp2[nb] = (POP == 8) ? (w2c + co * 32 + t * 8) : (w2c + co * 64 + t * 16);
        }

#pragma unroll
        for (int tap = 0; tap < 9; tap++) {
            const int dy = tap / 3 - 1, dx = tap % 3 - 1;
            const int off = dy * RW + dx;
            if (POP == 8) {
                const int wimm = tap * COUT * 32;
                uint2 vb[NB];
#pragma unroll
                for (int nb = 0; nb < NB; nb++) vb[nb] = *(const uint2*)(wp2[nb] + wimm);
#pragma unroll
                for (int r = 0; r < 2; r++) {
                    unsigned a0, a1, a2, a3;
                    ldsm_x4(a0, a1, a2, a3, m_lm[r] + off * 48);
#pragma unroll
                    for (int nb = 0; nb < NB; nb++)
                        mma16h(acc[r][nb], a0, a1, a2, a3, vb[nb].x, vb[nb].y);
                }
            } else {
                const int wimm = tap * COUT * 64;
                uint4 vb[NB];
#pragma unroll
                for (int nb = 0; nb < NB; nb++) vb[nb] = *(const uint4*)(wp2[nb] + wimm);
#pragma unroll
                for (int r = 0; r < 2; r++) {
                    int pb0 = (wr0 + r + dy + 1) * RW + dx + 1 + g;
                    int pb1 = pb0 + 8;
                    const char* q0 = muc + pb0 * 64 + (t * 16 ^ ((pb0 & 1) << 5));
                    const char* q1 = muc + pb1 * 64 + (t * 16 ^ ((pb1 & 1) << 5));
                    uint4 va0 = *(const uint4*)q0;
                    uint4 va1 = *(const uint4*)q1;
#pragma unroll
                    for (int nb = 0; nb < NB; nb++) {
                        mma16h(acc[r][nb], va0.x, va1.x, va0.y, va1.y, vb[nb].x, vb[nb].y);
                        mma16h(acc[r][nb], va0.z, va1.z, va0.w, va1.w, vb[nb].z, vb[nb].w);
                    }
                }
            }
        }

        const __half2* res2 = (const __half2*)resid;
#pragma unroll
        for (int r = 0; r < 2; r++) {
            int oy = by + wr0 + r;
            long oprow = (long)(n * H + oy) * W + bx;
#pragma unroll
            for (int nb = 0; nb < NB; nb++) {
                int pr = nb * 4 + t;
                int sl = (POP == 8) ? pr : pslot(pr, 16);
                int co = 2 * pr;
                float bv0 = b2v[co], bv1 = b2v[co + 1];
                long i0 = (oprow + g) * POP + sl;
                long i1 = (oprow + g + 8) * POP + sl;
                float2 r0 = __half22float2(res2[i0]);
                float2 r1 = __half22float2(res2[i1]);
                float v00 = acc[r][nb][0] + bv0 + r0.x, v01 = acc[r][nb][1] + bv1 + r0.y;
                float v10 = acc[r][nb][2] + bv0 + r1.x, v11 = acc[r][nb][3] + bv1 + r1.y;
                if (RELU_OUT) {
                    v00 = fmaxf(v00, 0.0f); v01 = fmaxf(v01, 0.0f);
                    v10 = fmaxf(v10, 0.0f); v11 = fmaxf(v11, 0.0f);
                }
                if (MODE == 1) {
                    __half2* outh = (__half2*)out;
                    outh[i0] = __floats2half2_rn(v00, v01);
                    outh[i1] = __floats2half2_rn(v10, v11);
                } else {
                    float* outf = (float*)out;
                    *(float2*)(outf + (oprow + g) * COUT + co) = make_float2(v00, v01);
                    *(float2*)(outf + (oprow + g + 8) * COUT + co) = make_float2(v10, v11);
                }
            }
        }
    }
}

// ---------------- fused CBAM: fp32 X in -> fp16 slot8-grouped XH out ------
__global__ __launch_bounds__(256) void cbam_fused_kernel(
    const float* __restrict__ x, const float* __restrict__ fc1, const float* __restrict__ fc2,
    const float* __restrict__ spw, __half2* __restrict__ xh) {
    __shared__ float s_x[256 * 36];
    __shared__ float rs[8][32], rm[8][32];
    __shared__ float s_mean[32], s_max[32], s_h[8], s_ca[32], s_sp[512], s_w[98];
    const int n = blockIdx.x, tid = threadIdx.x;

    const float* gbase = x + ((long)n * 256 + tid) * 32;
#pragma unroll
    for (int c = 0; c < 32; c += 4)
        *(float4*)(s_x + tid * 36 + c) = *(const float4*)(gbase + c);
    if (tid < 98) s_w[tid] = spw[tid];
    __syncthreads();

    {
        int g = tid >> 5, c = tid & 31;
        float sm = 0.0f, mx = -3.4e38f;
        for (int p = g; p < 256; p += 8) {
            float v = s_x[p * 36 + c];
            sm += v; mx = fmaxf(mx, v);
        }
        rs[g][c] = sm; rm[g][c] = mx;
    }
    __syncthreads();
    if (tid < 32) {
        float s = 0.0f, m = -3.4e38f;
        for (int q = 0; q < 8; q++) { s += rs[q][tid]; m = fmaxf(m, rm[q][tid]); }
        s_mean[tid] = s * (1.0f / 256.0f); s_max[tid] = m;
    }
    __syncthreads();
    if (tid < 8) {
        float hm = 0.0f, hx = 0.0f;
        for (int k = 0; k < 32; k++) {
            float wv = fc1[tid * 32 + k];
            hm += s_mean[k] * wv; hx += s_max[k] * wv;
        }
        s_h[tid] = fmaxf(hm, 0.0f) + fmaxf(hx, 0.0f);
    }
    __syncthreads();
    if (tid < 32) {
        float o = 0.0f;
        for (int j = 0; j < 8; j++) o += s_h[j] * fc2[tid * 8 + j];
        s_ca[tid] = sigf(o);
    }
    __syncthreads();

    {
        float sum = 0.0f, mx = -3.4e38f;
#pragma unroll
        for (int c = 0; c < 32; c++) {
            float v = s_x[tid * 36 + c] * s_ca[c];
            s_x[tid * 36 + c] = v;
            sum += v; mx = fmaxf(mx, v);
        }
        s_sp[tid] = sum * (1.0f / 32.0f);
        s_sp[256 + tid] = mx;
    }
    __syncthreads();

    {
        int oy = tid >> 4, ox = tid & 15;
        float a = 0.0f;
#pragma unroll
        for (int ci = 0; ci < 2; ci++)
            for (int ky = 0; ky < 7; ky++) {
                int y = oy + ky - 3;
                if (y < 0 || y >= 16) continue;
                for (int kx = 0; kx < 7; kx++) {
                    int xx = ox + kx - 3;
                    if (xx < 0 || xx >= 16) continue;
                    a = fmaf(s_sp[ci * 256 + y * 16 + xx], s_w[(ci * 7 + ky) * 7 + kx], a);
                }
            }
        float sa = sigf(a);
        // write fp16 slot8-grouped pairs (k = c*256 + p), pair = (p, p+1)
        __half2* row = xh + (long)n * 4096;
        int p2 = tid >> 1;
        bool even = ((tid & 1) == 0);
#pragma unroll
        for (int c = 0; c < 32; c++) {
            float v = s_x[tid * 36 + c] * sa;
            float vn = __shfl_down_sync(0xffffffffu, v, 1);
            if (even) {
                int pairidx = c * 128 + p2;
                int g = pairidx >> 3, q = pairidx & 7;
                row[g * 8 + pslot(q, 8)] = __floats2half2_rn(v, vn);
            }
        }
    }
}

// ---------------- FC: smem-free fp16 warp GEMM, K=8192 --------------------
// grid 128 blocks x 128 thr (4 warps); warp job = (m16, n16) of FEAT[512,256]
__global__ __launch_bounds__(128) void fc_gemm_h_kernel(
    const __half2* __restrict__ A, const __half2* __restrict__ B,
    const float* __restrict__ bias, float* __restrict__ C) {
    const int warp = threadIdx.x >> 5, lane = threadIdx.x & 31;
    const int g = lane >> 2, t = lane & 3;
    const int job = blockIdx.x * 4 + warp;      // 512 jobs = 32 m x 16 n16
    const int mt = job >> 4, nt = job & 15;
    const int m0 = mt * 16, n0 = nt * 16;

    const uint2* a0r = (const uint2*)(A + (long)(m0 + g) * 4096) + t;
    const uint2* a1r = (const uint2*)(A + (long)(m0 + g + 8) * 4096) + t;
    const uint2* b0r = (const uint2*)(B + (long)(n0 + g) * 4096) + t;
    const uint2* b1r = (const uint2*)(B + (long)(n0 + g + 8) * 4096) + t;

    float acc[2][4];
#pragma unroll
    for (int j = 0; j < 2; j++)
#pragma unroll
        for (int q = 0; q < 4; q++) acc[j][q] = 0.0f;

#pragma unroll 4
    for (int k = 0; k < 512; k++) {
        uint2 va0 = a0r[k * 4];
        uint2 va1 = a1r[k * 4];
        uint2 vb0 = b0r[k * 4];
        uint2 vb1 = b1r[k * 4];
        mma16h(acc[0], va0.x, va1.x, va0.y, va1.y, vb0.x, vb0.y);
        mma16h(acc[1], va0.x, va1.x, va0.y, va1.y, vb1.x, vb1.y);
    }
#pragma unroll
    for (int j = 0; j < 2; j++) {
        int col = n0 + j * 8 + 2 * t;
        float b0 = bias[col], b1 = bias[col + 1];
        float v00 = fmaxf(acc[j][0] + b0, 0.0f), v01 = fmaxf(acc[j][1] + b1, 0.0f);
        float v10 = fmaxf(acc[j][2] + b0, 0.0f), v11 = fmaxf(acc[j][3] + b1, 0.0f);
        *(float2*)(C + (long)(m0 + g) * 256 + col) = make_float2(v00, v01);
        *(float2*)(C + (long)(m0 + g + 8) * 256 + col) = make_float2(v10, v11);
    }
}

// ---------------- tf32 MMA GEMM (GRU input gates, K=256) ------------------
template <int RELU>
__global__ __launch_bounds__(256) void gemm_mma_kernel(
    const float* __restrict__ A, const float* __restrict__ B,
    const float* __restrict__ bias, float* __restrict__ C,
    int M, int N, int K) {
    __shared__ float sA[2][32 * 36], sB[2][64 * 36];
    const int tid = threadIdx.x;
    const int bm = blockIdx.y * 32, bn = blockIdx.x * 64;
    const int warp = tid >> 5, lane = tid & 31, g = lane >> 2, t = lane & 3;
    const int wm = warp >> 2, wn = warp & 3;
    const int lrA = tid >> 3, lcA = (tid & 7) * 4;
    const int lrB = tid >> 2, lcB = (tid & 3) * 8;

    float acc[2][4];
#pragma unroll
    for (int i = 0; i < 2; i++)
#pragma unroll
        for (int q = 0; q < 4; q++) acc[i][q] = 0.0f;

    const float* pA = A + (long)(bm + lrA) * K + lcA;
    const float* pB = B + (long)(bn + lrB) * K + lcB;

    float4 va = *(const float4*)(pA);
    float4 vb0 = *(const float4*)(pB);
    float4 vb1 = *(const float4*)(pB + 4);
    {
        float* pa = sA[0] + lrA * 36 + lcA;
        float* pb = sB[0] + lrB * 36 + lcB;
        pa[0]=tf32f(va.x); pa[1]=tf32f(va.y); pa[2]=tf32f(va.z); pa[3]=tf32f(va.w);
        pb[0]=tf32f(vb0.x); pb[1]=tf32f(vb0.y); pb[2]=tf32f(vb0.z); pb[3]=tf32f(vb0.w);
        pb[4]=tf32f(vb1.x); pb[5]=tf32f(vb1.y); pb[6]=tf32f(vb1.z); pb[7]=tf32f(vb1.w);
    }
    __syncthreads();

    int buf = 0;
    for (int k0 = 0; k0 < K; k0 += 32) {
        bool has_next = (k0 + 32 < K);
        if (has_next) {
            va = *(const float4*)(pA + k0 + 32);
            vb0 = *(const float4*)(pB + k0 + 32);
            vb1 = *(const float4*)(pB + k0 + 36);
        }
        const float* cA = sA[buf];
        const float* cB = sB[buf];
#pragma unroll
        for (int ks = 0; ks < 4; ks++) {
            const int k = ks * 8;
            const int r0 = wm * 16 + g;
            unsigned a0 = U(cA[r0 * 36 + k + t]),     a1 = U(cA[(r0 + 8) * 36 + k + t]);
            unsigned a2 = U(cA[r0 * 36 + k + t + 4]), a3 = U(cA[(r0 + 8) * 36 + k + t + 4]);
#pragma unroll
            for (int nt = 0; nt < 2; nt++) {
                int nr = wn * 16 + nt * 8 + g;
                mma8(acc[nt], a0, a1, a2, a3, cB[nr * 36 + k + t], cB[nr * 36 + k + t + 4]);
            }
        }
        if (has_next) {
            float* pa = sA[buf ^ 1] + lrA * 36 + lcA;
            float* pb = sB[buf ^ 1] + lrB * 36 + lcB;
            pa[0]=tf32f(va.x); pa[1]=tf32f(va.y); pa[2]=tf32f(va.z); pa[3]=tf32f(va.w);
            pb[0]=tf32f(vb0.x); pb[1]=tf32f(vb0.y); pb[2]=tf32f(vb0.z); pb[3]=tf32f(vb0.w);
            pb[4]=tf32f(vb1.x); pb[5]=tf32f(vb1.y); pb[6]=tf32f(vb1.z); pb[7]=tf32f(vb1.w);
        }
        __syncthreads();
        buf ^= 1;
    }
#pragma unroll
    for (int nt = 0; nt < 2; nt++) {
        int n0 = bn + wn * 16 + nt * 8 + 2 * t;
        int m0 = bm + wm * 16 + g;
        float b0 = bias[n0], b1 = bias[n0 + 1];
        float v00 = acc[nt][0] + b0, v01 = acc[nt][1] + b1;
        float v10 = acc[nt][2] + b0, v11 = acc[nt][3] + b1;
        if (RELU) {
            v00 = fmaxf(v00, 0.0f); v01 = fmaxf(v01, 0.0f);
            v10 = fmaxf(v10, 0.0f); v11 = fmaxf(v11, 0.0f);
        }
        C[(long)m0 * N + n0] = v00;       C[(long)m0 * N + n0 + 1] = v01;
        C[(long)(m0 + 8) * N + n0] = v10; C[(long)(m0 + 8) * N + n0 + 1] = v11;
    }
}

// ---------------- GRU scan ----------------
__global__ void gru_scan_kernel(const float* __restrict__ gi, const float* __restrict__ done,
                                const float* __restrict__ h0, const float* __restrict__ whh,
                                const float* __restrict__ bhh, float* __restrict__ hidden) {
    extern __shared__ __half2 smg[];
    __half2* s_whh = smg;
    float* s_gh = (float*)(smg + 64 * 384);
    float* s_h = s_gh + 384;
    float* s_hm = s_h + 128;
    int b = blockIdx.x, j = threadIdx.x;

    for (int i = j; i < 64 * 384; i += 384) {
        int jj = i / 64, k2 = i - jj * 64;
        s_whh[k2 * 384 + jj] = __floats2half2_rn(whh[jj * 128 + 2 * k2],
                                                 whh[jj * 128 + 2 * k2 + 1]);
    }
    if (j < 128) s_h[j] = h0[b * 128 + j];
    __syncthreads();

    float bh = bhh[j];
    for (int t = 0; t < 64; t++) {
        float dt = done[t * 8 + b];
        if (j < 128) s_hm[j] = (1.0f - dt) * s_h[j];
        __syncthreads();
        float acc = bh;
#pragma unroll 8
        for (int k2 = 0; k2 < 64; k2++) {
            float2 wv = __half22float2(s_whh[k2 * 384 + j]);
            float2 hm = *(const float2*)(s_hm + 2 * k2);
            acc = fmaf(hm.x, wv.x, acc);
            acc = fmaf(hm.y, wv.y, acc);
        }
        s_gh[j] = acc;
        __syncthreads();
        if (j < 128) {
            const float* gr = gi + (long)(t * 8 + b) * 384;
            float r = sigf(gr[j] + s_gh[j]);
            float z = sigf(gr[128 + j] + s_gh[128 + j]);
            float nn = tanhf(gr[256 + j] + r * s_gh[256 + j]);
            float hn = (1.0f - z) * nn + z * s_hm[j];
            s_h[j] = hn;
            hidden[(long)(t * 8 + b) * 128 + j] = hn;
        }
        __syncthreads();
    }
}

// ---------------- actor/critic heads ----------------
__global__ void heads_kernel(const float* __restrict__ hidden, const float* __restrict__ aw,
                             const float* __restrict__ ab, const float* __restrict__ cw,
                             const float* __restrict__ cb, float* __restrict__ out) {
    int row = blockIdx.x, t = threadIdx.x;
    __shared__ float s_h[128];
    s_h[t] = hidden[(long)row * 128 + t];
    __syncthreads();
    if (t < 4) {
        const float* w = (t < 3) ? (aw + t * 128) : cw;
        float s = (t < 3) ? ab[t] : cb[0];
        for (int k = 0; k < 128; k++) s = fmaf(s_h[k], w[k], s);
        out[row * 4 + t] = s;
    }
}

// ---------------- host-side launch helpers ----------------
template <int TW, int CIN, int COUT, bool RELU_IN, int MODE, bool RELU_OUT, bool NCHW>
static void launch_fused(const void* in, const __half2* w1, const float* b1,
                         const __half2* w2, const float* b2,
                         void* out, const void* resid, int H, int W) {
    constexpr int CINP = (CIN <= 8) ? 8 : ((CIN <= 16) ? 16 : 32);
    constexpr int PAIRS = CINP / 2;
    constexpr int POP = COUT / 2;
    constexpr int ISTR = (PAIRS == 4) ? 4 : ((PAIRS == 8) ? 12 : 16);
    constexpr int MSTR = (MODE == 0) ? POP : ((POP == 8) ? 12 : 16);
    int smem = (20 * (TW + 4) * ISTR + 18 * (TW + 2) * MSTR) * 4;
    auto kfn = conv_fused_kernel<TW, CIN, COUT, RELU_IN, MODE, RELU_OUT, NCHW>;
    cudaFuncSetAttribute(kfn, cudaFuncAttributeMaxDynamicSharedMemorySize, smem);
    dim3 grid(W / TW, H / 16, 512);
    kfn<<<grid, 256, smem>>>(in, w1, b1, w2, b2, out, resid, H, W);
}

extern "C" void kernel_launch(void* const* d_in, const int* in_sizes, int n_in,
                              void* d_out, int out_size) {
    (void)in_sizes; (void)n_in; (void)out_size;
    const float* x        = (const float*)d_in[0];
    const float* done     = (const float*)d_in[1];
    const float* grustate = (const float*)d_in[2];
    const float* s0_cw = (const float*)d_in[3];
    const float* s0_cb = (const float*)d_in[4];
    const float* s0_rw = (const float*)d_in[5];
    const float* s0_rb = (const float*)d_in[6];
    const float* s1_cw = (const float*)d_in[7];
    const float* s1_cb = (const float*)d_in[8];
    const float* s1_rw = (const float*)d_in[9];
    const float* s1_rb = (const float*)d_in[10];
    const float* s2_cw = (const float*)d_in[11];
    const float* s2_cb = (const float*)d_in[12];
    const float* s2_rw = (const float*)d_in[13];
    const float* s2_rb = (const float*)d_in[14];
    const float* cbam_fc1 = (const float*)d_in[15];
    const float* cbam_fc2 = (const float*)d_in[16];
    const float* cbam_spw = (const float*)d_in[17];
    const float* fc_w  = (const float*)d_in[18];
    const float* fc_b  = (const float*)d_in[19];
    const float* gwih  = (const float*)d_in[20];
    const float* gwhh  = (const float*)d_in[21];
    const float* gbih  = (const float*)d_in[22];
    const float* gbhh  = (const float*)d_in[23];
    const float* aw    = (const float*)d_in[24];
    const float* ab    = (const float*)d_in[25];
    const float* cw    = (const float*)d_in[26];
    const float* cb    = (const float*)d_in[27];
    float* out = (float*)d_out;

    float *X, *O, *FEAT, *GI, *HID, *FCWT;
    __half2* WP;
    cudaGetSymbolAddress((void**)&X, g_X);
    cudaGetSymbolAddress((void**)&O, g_O);
    cudaGetSymbolAddress((void**)&FEAT, g_feat);
    cudaGetSymbolAddress((void**)&GI, g_gi);
    cudaGetSymbolAddress((void**)&HID, g_hid);
    cudaGetSymbolAddress((void**)&FCWT, g_fcwT);
    cudaGetSymbolAddress((void**)&WP, g_wperm2);
    void *Xh = (void*)X, *Oh = (void*)O;
    __half2* BH = (__half2*)FCWT;

    const int OFF_S0C = 0;
    const int OFF_S0R = 576;
    const int OFF_S1C = 5184;
    const int OFF_S1R = 7488;
    const int OFF_S2C = 25920;
    const int OFF_S2R = 30528;

    wperm_all_kernel<<<(48960 + 255) / 256, 256>>>(s0_cw, s0_rw, s1_cw, s1_rw, s2_cw, s2_rw, WP);
    fcwh_permute<<<(256 * 4096 + 255) / 256, 256>>>(fc_w, BH);

    // ---- stage 0: head with 32-wide tiles; res TW=16 ----
    launch_fused<32, 6, 16, false, 0, false, true>(x, WP + OFF_S0C, s0_cb, WP + OFF_S0C, s0_cb, Xh, nullptr, 128, 128);
    launch_fused<16, 16, 16, true, 1, false, false>(Xh, WP + OFF_S0R + 0 * 1152, s0_rb + 0,
                                                    WP + OFF_S0R + 1 * 1152, s0_rb + 16, Oh, Xh, 64, 64);
    launch_fused<16, 16, 16, true, 1, false, false>(Oh, WP + OFF_S0R + 2 * 1152, s0_rb + 32,
                                                    WP + OFF_S0R + 3 * 1152, s0_rb + 48, Xh, Oh, 64, 64);

    // ---- stage 1 ----
    launch_fused<16, 16, 32, false, 0, false, false>(Xh, WP + OFF_S1C, s1_cb, WP + OFF_S1C, s1_cb, Oh, nullptr, 64, 64);
    launch_fused<16, 32, 32, true, 1, false, false>(Oh, WP + OFF_S1R + 0 * 4608, s1_rb + 0,
                                                    WP + OFF_S1R + 1 * 4608, s1_rb + 32, Xh, Oh, 32, 32);
    launch_fused<16, 32, 32, true, 1, false, false>(Xh, WP + OFF_S1R + 2 * 4608, s1_rb + 64,
                                                    WP + OFF_S1R + 3 * 4608, s1_rb + 96, Oh, Xh, 32, 32);

    // ---- stage 2 (final res writes fp32 NHWC + relu into X) ----
    launch_fused<16, 32, 32, false, 0, false, false>(Oh, WP + OFF_S2C, s2_cb, WP + OFF_S2C, s2_cb, Xh, nullptr, 32, 32);
    launch_fused<16, 32, 32, true, 1, false, false>(Xh, WP + OFF_S2R + 0 * 4608, s2_rb + 0,
                                                    WP + OFF_S2R + 1 * 4608, s2_rb + 32, Oh, Xh, 16, 16);
    launch_fused<16, 32, 32, true, 2, true, false>(Oh, WP + OFF_S2R + 2 * 4608, s2_rb + 64,
                                                   WP + OFF_S2R + 3 * 4608, s2_rb + 96, (void*)X, Oh, 16, 16);

    // ---- fused CBAM: X fp32 in -> XH fp16 grouped (in O buffer) ----
    cbam_fused_kernel<<<512, 256>>>(X, cbam_fc1, cbam_fc2, cbam_spw, (__half2*)Oh);

    // ---- FC fp16 warp GEMM + GRU input-gate GEMM ----
    fc_gemm_h_kernel<<<128, 128>>>((const __half2*)Oh, BH, fc_b, FEAT);
    gemm_mma_kernel<0><<<dim3(384 / 64, 512 / 32), 256>>>(FEAT, gwih, gbih, GI, 512, 384, 256);

    // ---- GRU sequential scan ----
    {
        int smem = 64 * 384 * 4 + (384 + 128 + 128) * 4;
        cudaFuncSetAttribute(gru_scan_kernel, cudaFuncAttributeMaxDynamicSharedMemorySize, smem);
        gru_scan_kernel<<<8, 384, smem>>>(GI, done, grustate, gwhh, gbhh, HID);
    }

    // ---- actor / critic heads -> (512, 4) ----
    heads_kernel<<<512, 128>>>(HID, aw, ab, cw, cb, out);
}

// round 14
// speedup vs baseline: 1.2610x; 1.2610x over previous
#include <cuda_runtime.h>
#include <cuda_fp16.h>
#include <math.h>

// ---------------- scratch (device globals; no allocations) ----------------
__device__ float g_X[33554432];
__device__ float g_O[33554432];
__device__ float g_feat[512 * 256];
__device__ float g_gi[512 * 384];
__device__ float g_hid[512 * 128];
__device__ float g_fcwT[256 * 8192];
__device__ __half2 g_wperm2[49152];

__device__ __forceinline__ float sigf(float x) { return 1.0f / (1.0f + expf(-x)); }

__device__ __forceinline__ unsigned tf32u(float x) {
    unsigned r;
    asm("cvt.rna.tf32.f32 %0, %1;" : "=r"(r) : "f"(x));
    return r;
}
__device__ __forceinline__ float tf32f(float x) { return __uint_as_float(tf32u(x)); }

__device__ __forceinline__ void mma8(float* c, unsigned a0, unsigned a1, unsigned a2, unsigned a3,
                                     float b0f, float b1f) {
    unsigned b0 = __float_as_uint(b0f), b1 = __float_as_uint(b1f);
    asm volatile(
        "mma.sync.aligned.m16n8k8.row.col.f32.tf32.tf32.f32 "
        "{%0,%1,%2,%3},{%4,%5,%6,%7},{%8,%9},{%0,%1,%2,%3};"
        : "+f"(c[0]), "+f"(c[1]), "+f"(c[2]), "+f"(c[3])
        : "r"(a0), "r"(a1), "r"(a2), "r"(a3), "r"(b0), "r"(b1));
}
__device__ __forceinline__ void mma16h(float* c, unsigned a0, unsigned a1, unsigned a2, unsigned a3,
                                       unsigned b0, unsigned b1) {
    asm volatile(
        "mma.sync.aligned.m16n8k16.row.col.f32.f16.f16.f32 "
        "{%0,%1,%2,%3},{%4,%5,%6,%7},{%8,%9},{%0,%1,%2,%3};"
        : "+f"(c[0]), "+f"(c[1]), "+f"(c[2]), "+f"(c[3])
        : "r"(a0), "r"(a1), "r"(a2), "r"(a3), "r"(b0), "r"(b1));
}
__device__ __forceinline__ void mma8h(float* c, unsigned a0, unsigned a1, unsigned b0) {
    asm volatile(
        "mma.sync.aligned.m16n8k8.row.col.f32.f16.f16.f32 "
        "{%0,%1,%2,%3},{%4,%5},{%6},{%0,%1,%2,%3};"
        : "+f"(c[0]), "+f"(c[1]), "+f"(c[2]), "+f"(c[3])
        : "r"(a0), "r"(a1), "r"(b0));
}
__device__ __forceinline__ void ldsm_x4(unsigned& r0, unsigned& r1, unsigned& r2, unsigned& r3,
                                        unsigned addr) {
    asm volatile("ldmatrix.sync.aligned.m8n8.x4.shared.b16 {%0,%1,%2,%3}, [%4];"
                 : "=r"(r0), "=r"(r1), "=r"(r2), "=r"(r3) : "r"(addr));
}
__device__ __forceinline__ void ldsm_x2(unsigned& r0, unsigned& r1, unsigned addr) {
    asm volatile("ldmatrix.sync.aligned.m8n8.x2.shared.b16 {%0,%1}, [%2];"
                 : "=r"(r0), "=r"(r1) : "r"(addr));
}
#define U(x) __float_as_uint(x)

__device__ __forceinline__ int pslot(int p, int PAIRS) {
    if (PAIRS == 4)  return p;
    if (PAIRS == 8)  return 2 * (p & 3) + (p >> 2);
    return 4 * (p & 3) + (p >> 2);
}
__device__ __forceinline__ unsigned packh2(float a, float b) {
    __half2 h = __floats2half2_rn(a, b);
    return *(unsigned*)&h;
}
__device__ __forceinline__ unsigned relu_u(unsigned u) {
    __half2 h = *(__half2*)&u;
    h = __hmax2(h, __half2half2(__float2half(0.0f)));
    return *(unsigned*)&h;
}
__device__ __forceinline__ uint4 relu4(uint4 v) {
    v.x = relu_u(v.x); v.y = relu_u(v.y); v.z = relu_u(v.z); v.w = relu_u(v.w);
    return v;
}

// ---------------- weight permute prepass -> fp16 pairs [tap][co][pslot] ----
__global__ void wperm_all_kernel(const float* __restrict__ s0c, const float* __restrict__ s0r,
                                 const float* __restrict__ s1c, const float* __restrict__ s1r,
                                 const float* __restrict__ s2c, const float* __restrict__ s2r,
                                 __half2* __restrict__ dst) {
    int i = blockIdx.x * 256 + threadIdx.x;
    if (i >= 48960) return;
    const float* src; int CIN, PAIRS, COUT, base;
    if (i < 576)        { src = s0c; CIN = 6;  PAIRS = 4;  COUT = 16; base = 0; }
    else if (i < 5184)  { src = s0r; CIN = 16; PAIRS = 8;  COUT = 16; base = 576; }
    else if (i < 7488)  { src = s1c; CIN = 16; PAIRS = 8;  COUT = 32; base = 5184; }
    else if (i < 25920) { src = s1r; CIN = 32; PAIRS = 16; COUT = 32; base = 7488; }
    else if (i < 30528) { src = s2c; CIN = 32; PAIRS = 16; COUT = 32; base = 25920; }
    else                { src = s2r; CIN = 32; PAIRS = 16; COUT = 32; base = 30528; }
    int li = i - base;
    int tap = li % 9; int r = li / 9;
    int p = r % PAIRS; r /= PAIRS;
    int co = r % COUT; int cv = r / COUT;
    int ci0 = 2 * p, ci1 = 2 * p + 1;
    float v0 = (ci0 < CIN) ? src[((cv * COUT + co) * CIN + ci0) * 9 + tap] : 0.0f;
    float v1 = (ci1 < CIN) ? src[((cv * COUT + co) * CIN + ci1) * 9 + tap] : 0.0f;
    dst[base + cv * 9 * COUT * PAIRS + (tap * COUT + co) * PAIRS + pslot(p, PAIRS)] =
        __floats2half2_rn(v0, v1);
}

// permute fc_w[n][c*256+p] -> g_fcwT[n][p*32+c]
__global__ void fcw_permute(const float* __restrict__ w, float* __restrict__ wt) {
    int i = blockIdx.x * 256 + threadIdx.x;
    if (i >= 256 * 8192) return;
    int n = i >> 13;
    int r = i & 8191;
    int c = r >> 8, p = r & 255;
    wt[(n << 13) + p * 32 + c] = w[i];
}

// ---------------- fused conv kernel (TW = tile width, height 16) -----------
// MODE 0: conv -> maxpool -> fp16 out.  MODE 1: resblock fp16 out.  MODE 2: fp32 NHWC out.
template <int TW, int CIN, int COUT, bool RELU_IN, int MODE, bool RELU_OUT, bool NCHW>
__global__ __launch_bounds__(256, (CIN <= 16 ? 4 : 3)) void conv_fused_kernel(
    const void* __restrict__ in, const __half2* __restrict__ w1,
    const float* __restrict__ b1v, const __half2* __restrict__ w2,
    const float* __restrict__ b2v, void* __restrict__ out,
    const void* __restrict__ resid, int H, int W) {
    constexpr int CINP = (CIN <= 8) ? 8 : ((CIN <= 16) ? 16 : 32);
    constexpr int PAIRS = CINP / 2;
    constexpr int POP = COUT / 2;
    constexpr int NB = COUT / 8;
    constexpr int HW = TW + 4;
    constexpr int RW = TW + 2;
    constexpr int HPIX = 20 * HW;
    constexpr int NPIX = 18 * RW;
    constexpr int NSUB = (NPIX + 127) / 128;
    constexpr int ISTR = (PAIRS == 4) ? 4 : ((PAIRS == 8) ? 12 : 16);
    constexpr int IN_W = HPIX * ISTR;
    constexpr int MSTR = (MODE == 0) ? POP : ((POP == 8) ? 12 : 16);
    constexpr int MID_W = NPIX * MSTR;

    extern __shared__ __half2 smh[];
    __half2* s_in2 = smh;
    __half2* s_mid2 = smh + IN_W;

    const int tid = threadIdx.x;
    const int n = blockIdx.z;
    const int by = blockIdx.y * 16, bx = blockIdx.x * TW;
    const unsigned sb_in = (unsigned)__cvta_generic_to_shared(s_in2);
    const unsigned sb_mid = (unsigned)__cvta_generic_to_shared(s_mid2);

    for (int i = tid; i < MID_W; i += 256) ((unsigned*)s_mid2)[i] = 0u;

    // ---- stage halo (20 x HW) ----
    for (int p = tid; p < HPIX; p += 256) {
        int iy = p / HW, ix = p - iy * HW;
        int gy = by + iy - 2, gx = bx + ix - 2;
        bool ok = (gy >= 0 && gy < H && gx >= 0 && gx < W);
        if (NCHW) {
            const float* inf = (const float*)in;
            uint4 wv = make_uint4(0u, 0u, 0u, 0u);
            if (ok) {
                long base = ((long)n * CIN * H + gy) * W + gx;
                long st = (long)H * W;
                wv = make_uint4(packh2(inf[base], inf[base + st]),
                                packh2(inf[base + 2 * st], inf[base + 3 * st]),
                                packh2(inf[base + 4 * st], inf[base + 5 * st]), 0u);
            }
            *(uint4*)(s_in2 + p * 4) = wv;
        } else if (PAIRS == 8) {
            uint4 lo = make_uint4(0u, 0u, 0u, 0u), hi = lo;
            if (ok) {
                const uint4* gp = (const uint4*)((const __half2*)in + ((long)(n * H + gy) * W + gx) * 8);
                lo = gp[0]; hi = gp[1];
                if (RELU_IN) { lo = relu4(lo); hi = relu4(hi); }
            }
            *(uint4*)(s_in2 + p * 12) = lo;
            *(uint4*)(s_in2 + p * 12 + 4) = hi;
        } else {
            uint4 v0 = make_uint4(0,0,0,0), v1 = v0, v2 = v0, v3 = v0;
            if (ok) {
                const uint4* gp = (const uint4*)((const __half2*)in + ((long)(n * H + gy) * W + gx) * 16);
                v0 = gp[0]; v1 = gp[1]; v2 = gp[2]; v3 = gp[3];
                if (RELU_IN) { v0 = relu4(v0); v1 = relu4(v1); v2 = relu4(v2); v3 = relu4(v3); }
            }
            *(uint4*)(s_in2 + p * 16) = v0;
            *(uint4*)(s_in2 + p * 16 + 4) = v1;
            *(uint4*)(s_in2 + p * 16 + 8) = v2;
            *(uint4*)(s_in2 + p * 16 + 12) = v3;
        }
    }
    __syncthreads();

    const int warp = tid >> 5, lane = tid & 31, g = lane >> 2, t = lane & 3;
    const char* suc = (const char*)s_in2;
    const char* w1c = (const char*)w1;

    float acc1[NSUB][NB][4];
#pragma unroll
    for (int s = 0; s < NSUB; s++)
#pragma unroll
        for (int nb = 0; nb < NB; nb++)
#pragma unroll
            for (int q = 0; q < 4; q++) acc1[s][nb][q] = 0.0f;

    unsigned lmaddr[NSUB];
    const char* a0p[NSUB]; const char* a1p[NSUB];
    if (PAIRS == 4 || PAIRS == 8) {
        int i8 = lane & 7, mm = lane >> 3;
#pragma unroll
        for (int s = 0; s < NSUB; s++) {
            int tt = warp + 8 * s;
            int p = tt * 16 + i8 + (mm & 1) * 8;
            if (p > NPIX - 1) p = NPIX - 1;
            int pix = (p / RW + 1) * HW + (p % RW) + 1;
            if (PAIRS == 4) lmaddr[s] = sb_in + pix * 16;
            else            lmaddr[s] = sb_in + pix * 48 + (mm >> 1) * 16;
        }
    } else {
#pragma unroll
        for (int s = 0; s < NSUB; s++) {
            int tt = warp + 8 * s;
            int p0 = tt * 16 + g, p1 = p0 + 8;
            int q0 = p0 > NPIX - 1 ? NPIX - 1 : p0, q1 = p1 > NPIX - 1 ? NPIX - 1 : p1;
            int b0 = (q0 / RW + 1) * HW + (q0 % RW + 1);
            int b1 = (q1 / RW + 1) * HW + (q1 % RW + 1);
            a0p[s] = suc + b0 * 64 + t * 16;
            a1p[s] = suc + b1 * 64 + t * 16;
        }
    }
    const char* wp1[NB];
#pragma unroll
    for (int nb = 0; nb < NB; nb++) {
        int co = nb * 8 + g;
        if (PAIRS == 4)      wp1[nb] = w1c + co * 16 + t * 4;
        else if (PAIRS == 8) wp1[nb] = w1c + co * 32 + t * 8;
        else                 wp1[nb] = w1c + co * 64 + t * 16;
    }

#pragma unroll
    for (int tap = 0; tap < 9; tap++) {
        const int dy = tap / 3 - 1, dx = tap % 3 - 1;
        const int off = dy * HW + dx;
        if (PAIRS == 4) {
            const int wimm = tap * COUT * 16;
            unsigned vb[NB];
#pragma unroll
            for (int nb = 0; nb < NB; nb++) vb[nb] = *(const unsigned*)(wp1[nb] + wimm);
#pragma unroll
            for (int s = 0; s < NSUB; s++) {
                unsigned a0, a1;
                ldsm_x2(a0, a1, lmaddr[s] + off * 16);
#pragma unroll
                for (int nb = 0; nb < NB; nb++) mma8h(acc1[s][nb], a0, a1, vb[nb]);
            }
        } else if (PAIRS == 8) {
            const int wimm = tap * COUT * 32;
            uint2 vb[NB];
#pragma unroll
            for (int nb = 0; nb < NB; nb++) vb[nb] = *(const uint2*)(wp1[nb] + wimm);
#pragma unroll
            for (int s = 0; s < NSUB; s++) {
                unsigned a0, a1, a2, a3;
                ldsm_x4(a0, a1, a2, a3, lmaddr[s] + off * 48);
#pragma unroll
                for (int nb = 0; nb < NB; nb++)
                    mma16h(acc1[s][nb], a0, a1, a2, a3, vb[nb].x, vb[nb].y);
            }
        } else {
            const int wimm = tap * COUT * 64, aimm = off * 64;
            uint4 vb[NB];
#pragma unroll
            for (int nb = 0; nb < NB; nb++) vb[nb] = *(const uint4*)(wp1[nb] + wimm);
#pragma unroll
            for (int s = 0; s < NSUB; s++) {
                uint4 va0 = *(const uint4*)(a0p[s] + aimm);
                uint4 va1 = *(const uint4*)(a1p[s] + aimm);
#pragma unroll
                for (int nb = 0; nb < NB; nb++) {
                    mma16h(acc1[s][nb], va0.x, va1.x, va0.y, va1.y, vb[nb].x, vb[nb].y);
                    mma16h(acc1[s][nb], va0.z, va1.z, va0.w, va1.w, vb[nb].z, vb[nb].w);
                }
            }
        }
    }

    // ---- store conv1 results to mid ----
#pragma unroll
    for (int s = 0; s < NSUB; s++) {
        int pbase = (warp + 8 * s) * 16 + g;
#pragma unroll
        for (int half = 0; half < 2; half++) {
            int p = pbase + 8 * half;
            if (p < NPIX) {
                int r = p / RW, c = p - r * RW;
                int gy = by - 1 + r, gx = bx - 1 + c;
                if (gy >= 0 && gy < H && gx >= 0 && gx < W) {
#pragma unroll
                    for (int nb = 0; nb < NB; nb++) {
                        int co = nb * 8 + 2 * t;
                        int pr = nb * 4 + t;
                        float v0 = acc1[s][nb][2 * half + 0] + b1v[co];
                        float v1 = acc1[s][nb][2 * half + 1] + b1v[co + 1];
                        if (MODE == 0) {
                            s_mid2[p * POP + pr] = __floats2half2_rn(v0, v1);
                        } else if (POP == 8) {
                            s_mid2[p * 12 + pr] =
                                __floats2half2_rn(fmaxf(v0, 0.0f), fmaxf(v1, 0.0f));
                        } else {
                            s_mid2[p * 16 + (pslot(pr, 16) ^ ((p & 1) << 3))] =
                                __floats2half2_rn(fmaxf(v0, 0.0f), fmaxf(v1, 0.0f));
                        }
                    }
                }
            }
        }
    }
    __syncthreads();

    if (MODE == 0) {
        int H2 = H >> 1, W2 = W >> 1;
        __half2* outh = (__half2*)out;
        for (int o = tid; o < 4 * TW * POP; o += 256) {
            int pr = o % POP; int pp = o / POP;
            int ly = pp / (TW / 2), lx = pp % (TW / 2);
            __half2 m = __floats2half2_rn(-65504.0f, -65504.0f);
#pragma unroll
            for (int dy = 0; dy < 3; dy++) {
                int r = 2 * ly + dy;
                int gy = by - 1 + r;
                if (gy < 0 || gy >= H) continue;
#pragma unroll
                for (int dxx = 0; dxx < 3; dxx++) {
                    int c = 2 * lx + dxx;
                    int gx = bx - 1 + c;
                    if (gx < 0 || gx >= W) continue;
                    m = __hmax2(m, s_mid2[(r * RW + c) * POP + pr]);
                }
            }
            long op = ((long)n * H2 + (by / 2 + ly)) * W2 + (bx / 2 + lx);
            outh[op * POP + (COUT == 16 ? pr : pslot(pr, 16))] = m;
        }
    } else {
        const char* muc = (const char*)s_mid2;
        const char* w2c = (const char*)w2;
        const int wr0 = warp * 2;
        float acc[2][NB][4];
#pragma unroll
        for (int r = 0; r < 2; r++)
#pragma unroll
            for (int nb = 0; nb < NB; nb++)
#pragma unroll
                for (int q = 0; q < 4; q++) acc[r][nb][q] = 0.0f;

        unsigned m_lm[2];
        if (POP == 8) {
            int i8 = lane & 7, mm = lane >> 3;
#pragma unroll
            for (int r = 0; r < 2; r++) {
                int pix = (wr0 + r + 1) * RW + 1 + i8 + (mm & 1) * 8;
                m_lm[r] = sb_mid + pix * 48 + (mm >> 1) * 16;
            }
        }
        const char* wp2[NB];
#pragma unroll
        for (int nb = 0; nb < NB; nb++) {
            int co = nb * 8 + g;
            wp2[nb] = (POP == 8) ? (w2c + co * 32 + t * 8) : (w2c + co * 64 + t * 16);
        }

#pragma unroll
        for (int tap = 0; tap < 9; tap++) {
            const int dy = tap / 3 - 1, dx = tap % 3 - 1;
            const int off = dy * RW + dx;
            if (POP == 8) {
                const int wimm = tap * COUT * 32;
                uint2 vb[NB];
#pragma unroll
                for (int nb = 0; nb < NB; nb++) vb[nb] = *(const uint2*)(wp2[nb] + wimm);
#pragma unroll
                for (int r = 0; r < 2; r++) {
                    unsigned a0, a1, a2, a3;
                    ldsm_x4(a0, a1, a2, a3, m_lm[r] + off * 48);
#pragma unroll
                    for (int nb = 0; nb < NB; nb++)
                        mma16h(acc[r][nb], a0, a1, a2, a3, vb[nb].x, vb[nb].y);
                }
            } else {
                const int wimm = tap * COUT * 64;
                uint4 vb[NB];
#pragma unroll
                for (int nb = 0; nb < NB; nb++) vb[nb] = *(const uint4*)(wp2[nb] + wimm);
#pragma unroll
                for (int r = 0; r < 2; r++) {
                    int pb0 = (wr0 + r + dy + 1) * RW + dx + 1 + g;
                    int pb1 = pb0 + 8;
                    const char* q0 = muc + pb0 * 64 + (t * 16 ^ ((pb0 & 1) << 5));
                    const char* q1 = muc + pb1 * 64 + (t * 16 ^ ((pb1 & 1) << 5));
                    uint4 va0 = *(const uint4*)q0;
                    uint4 va1 = *(const uint4*)q1;
#pragma unroll
                    for (int nb = 0; nb < NB; nb++) {
                        mma16h(acc[r][nb], va0.x, va1.x, va0.y, va1.y, vb[nb].x, vb[nb].y);
                        mma16h(acc[r][nb], va0.z, va1.z, va0.w, va1.w, vb[nb].z, vb[nb].w);
                    }
                }
            }
        }

        const __half2* res2 = (const __half2*)resid;
#pragma unroll
        for (int r = 0; r < 2; r++) {
            int oy = by + wr0 + r;
            long oprow = (long)(n * H + oy) * W + bx;
#pragma unroll
            for (int nb = 0; nb < NB; nb++) {
                int pr = nb * 4 + t;
                int sl = (POP == 8) ? pr : pslot(pr, 16);
                int co = 2 * pr;
                float bv0 = b2v[co], bv1 = b2v[co + 1];
                long i0 = (oprow + g) * POP + sl;
                long i1 = (oprow + g + 8) * POP + sl;
                float2 r0 = __half22float2(res2[i0]);
                float2 r1 = __half22float2(res2[i1]);
                float v00 = acc[r][nb][0] + bv0 + r0.x, v01 = acc[r][nb][1] + bv1 + r0.y;
                float v10 = acc[r][nb][2] + bv0 + r1.x, v11 = acc[r][nb][3] + bv1 + r1.y;
                if (RELU_OUT) {
                    v00 = fmaxf(v00, 0.0f); v01 = fmaxf(v01, 0.0f);
                    v10 = fmaxf(v10, 0.0f); v11 = fmaxf(v11, 0.0f);
                }
                if (MODE == 1) {
                    __half2* outh = (__half2*)out;
                    outh[i0] = __floats2half2_rn(v00, v01);
                    outh[i1] = __floats2half2_rn(v10, v11);
                } else {
                    float* outf = (float*)out;
                    *(float2*)(outf + (oprow + g) * COUT + co) = make_float2(v00, v01);
                    *(float2*)(outf + (oprow + g + 8) * COUT + co) = make_float2(v10, v11);
                }
            }
        }
    }
}

// ---------------- fused CBAM (fp32 NHWC X, in place) ----------------
__global__ __launch_bounds__(256) void cbam_fused_kernel(
    float* __restrict__ x, const float* __restrict__ fc1, const float* __restrict__ fc2,
    const float* __restrict__ spw) {
    __shared__ float s_x[256 * 36];
    __shared__ float rs[8][32], rm[8][32];
    __shared__ float s_mean[32], s_max[32], s_h[8], s_ca[32], s_sp[512], s_w[98];
    const int n = blockIdx.x, tid = threadIdx.x;

    float* gbase = x + ((long)n * 256 + tid) * 32;
#pragma unroll
    for (int c = 0; c < 32; c += 4)
        *(float4*)(s_x + tid * 36 + c) = *(const float4*)(gbase + c);
    if (tid < 98) s_w[tid] = spw[tid];
    __syncthreads();

    {
        int g = tid >> 5, c = tid & 31;
        float sm = 0.0f, mx = -3.4e38f;
        for (int p = g; p < 256; p += 8) {
            float v = s_x[p * 36 + c];
            sm += v; mx = fmaxf(mx, v);
        }
        rs[g][c] = sm; rm[g][c] = mx;
    }
    __syncthreads();
    if (tid < 32) {
        float s = 0.0f, m = -3.4e38f;
        for (int q = 0; q < 8; q++) { s += rs[q][tid]; m = fmaxf(m, rm[q][tid]); }
        s_mean[tid] = s * (1.0f / 256.0f); s_max[tid] = m;
    }
    __syncthreads();
    if (tid < 8) {
        float hm = 0.0f, hx = 0.0f;
        for (int k = 0; k < 32; k++) {
            float wv = fc1[tid * 32 + k];
            hm += s_mean[k] * wv; hx += s_max[k] * wv;
        }
        s_h[tid] = fmaxf(hm, 0.0f) + fmaxf(hx, 0.0f);
    }
    __syncthreads();
    if (tid < 32) {
        float o = 0.0f;
        for (int j = 0; j < 8; j++) o += s_h[j] * fc2[tid * 8 + j];
        s_ca[tid] = sigf(o);
    }
    __syncthreads();

    {
        float sum = 0.0f, mx = -3.4e38f;
#pragma unroll
        for (int c = 0; c < 32; c++) {
            float v = s_x[tid * 36 + c] * s_ca[c];
            s_x[tid * 36 + c] = v;
            sum += v; mx = fmaxf(mx, v);
        }
        s_sp[tid] = sum * (1.0f / 32.0f);
        s_sp[256 + tid] = mx;
    }
    __syncthreads();

    {
        int oy = tid >> 4, ox = tid & 15;
        float a = 0.0f;
#pragma unroll
        for (int ci = 0; ci < 2; ci++)
            for (int ky = 0; ky < 7; ky++) {
                int y = oy + ky - 3;
                if (y < 0 || y >= 16) continue;
                for (int kx = 0; kx < 7; kx++) {
                    int xx = ox + kx - 3;
                    if (xx < 0 || xx >= 16) continue;
                    a = fmaf(s_sp[ci * 256 + y * 16 + xx], s_w[(ci * 7 + ky) * 7 + kx], a);
                }
            }
        float sa = sigf(a);
#pragma unroll
        for (int c = 0; c < 32; c += 4) {
            float4 v;
            v.x = s_x[tid * 36 + c] * sa;
            v.y = s_x[tid * 36 + c + 1] * sa;
            v.z = s_x[tid * 36 + c + 2] * sa;
            v.w = s_x[tid * 36 + c + 3] * sa;
            *(float4*)(gbase + c) = v;
        }
    }
}

// ---------------- tf32 MMA GEMM, single-sync double-buffered --------------
template <int RELU>
__global__ __launch_bounds__(256) void gemm_mma_kernel(
    const float* __restrict__ A, const float* __restrict__ B,
    const float* __restrict__ bias, float* __restrict__ C,
    int M, int N, int K) {
    __shared__ float sA[2][32 * 36], sB[2][64 * 36];
    const int tid = threadIdx.x;
    const int bm = blockIdx.y * 32, bn = blockIdx.x * 64;
    const int warp = tid >> 5, lane = tid & 31, g = lane >> 2, t = lane & 3;
    const int wm = warp >> 2, wn = warp & 3;
    const int lrA = tid >> 3, lcA = (tid & 7) * 4;
    const int lrB = tid >> 2, lcB = (tid & 3) * 8;

    float acc[2][4];
#pragma unroll
    for (int i = 0; i < 2; i++)
#pragma unroll
        for (int q = 0; q < 4; q++) acc[i][q] = 0.0f;

    const float* pA = A + (long)(bm + lrA) * K + lcA;
    const float* pB = B + (long)(bn + lrB) * K + lcB;

    float4 va = *(const float4*)(pA);
    float4 vb0 = *(const float4*)(pB);
    float4 vb1 = *(const float4*)(pB + 4);
    {
        float* pa = sA[0] + lrA * 36 + lcA;
        float* pb = sB[0] + lrB * 36 + lcB;
        pa[0]=tf32f(va.x); pa[1]=tf32f(va.y); pa[2]=tf32f(va.z); pa[3]=tf32f(va.w);
        pb[0]=tf32f(vb0.x); pb[1]=tf32f(vb0.y); pb[2]=tf32f(vb0.z); pb[3]=tf32f(vb0.w);
        pb[4]=tf32f(vb1.x); pb[5]=tf32f(vb1.y); pb[6]=tf32f(vb1.z); pb[7]=tf32f(vb1.w);
    }
    __syncthreads();

    int buf = 0;
    for (int k0 = 0; k0 < K; k0 += 32) {
        bool has_next = (k0 + 32 < K);
        if (has_next) {
            va = *(const float4*)(pA + k0 + 32);
            vb0 = *(const float4*)(pB + k0 + 32);
            vb1 = *(const float4*)(pB + k0 + 36);
        }
        const float* cA = sA[buf];
        const float* cB = sB[buf];
#pragma unroll
        for (int ks = 0; ks < 4; ks++) {
            const int k = ks * 8;
            const int r0 = wm * 16 + g;
            unsigned a0 = U(cA[r0 * 36 + k + t]),     a1 = U(cA[(r0 + 8) * 36 + k + t]);
            unsigned a2 = U(cA[r0 * 36 + k + t + 4]), a3 = U(cA[(r0 + 8) * 36 + k + t + 4]);
#pragma unroll
            for (int nt = 0; nt < 2; nt++) {
                int nr = wn * 16 + nt * 8 + g;
                mma8(acc[nt], a0, a1, a2, a3, cB[nr * 36 + k + t], cB[nr * 36 + k + t + 4]);
            }
        }
        if (has_next) {
            float* pa = sA[buf ^ 1] + lrA * 36 + lcA;
            float* pb = sB[buf ^ 1] + lrB * 36 + lcB;
            pa[0]=tf32f(va.x); pa[1]=tf32f(va.y); pa[2]=tf32f(va.z); pa[3]=tf32f(va.w);
            pb[0]=tf32f(vb0.x); pb[1]=tf32f(vb0.y); pb[2]=tf32f(vb0.z); pb[3]=tf32f(vb0.w);
            pb[4]=tf32f(vb1.x); pb[5]=tf32f(vb1.y); pb[6]=tf32f(vb1.z); pb[7]=tf32f(vb1.w);
        }
        __syncthreads();
        buf ^= 1;
    }
#pragma unroll
    for (int nt = 0; nt < 2; nt++) {
        int n0 = bn + wn * 16 + nt * 8 + 2 * t;
        int m0 = bm + wm * 16 + g;
        float b0 = bias[n0], b1 = bias[n0 + 1];
        float v00 = acc[nt][0] + b0, v01 = acc[nt][1] + b1;
        float v10 = acc[nt][2] + b0, v11 = acc[nt][3] + b1;
        if (RELU) {
            v00 = fmaxf(v00, 0.0f); v01 = fmaxf(v01, 0.0f);
            v10 = fmaxf(v10, 0.0f); v11 = fmaxf(v11, 0.0f);
        }
        C[(long)m0 * N + n0] = v00;       C[(long)m0 * N + n0 + 1] = v01;
        C[(long)(m0 + 8) * N + n0] = v10; C[(long)(m0 + 8) * N + n0 + 1] = v11;
    }
}

// ---------------- GRU scan (whh as fp16 pairs in smem) ----------------
__global__ void gru_scan_kernel(const float* __restrict__ gi, const float* __restrict__ done,
                                const float* __restrict__ h0, const float* __restrict__ whh,
                                const float* __restrict__ bhh, float* __restrict__ hidden) {
    extern __shared__ __half2 smg[];
    __half2* s_whh = smg;
    float* s_gh = (float*)(smg + 64 * 384);
    float* s_h = s_gh + 384;
    float* s_hm = s_h + 128;
    int b = blockIdx.x, j = threadIdx.x;

    for (int i = j; i < 64 * 384; i += 384) {
        int jj = i / 64, k2 = i - jj * 64;
        s_whh[k2 * 384 + jj] = __floats2half2_rn(whh[jj * 128 + 2 * k2],
                                                 whh[jj * 128 + 2 * k2 + 1]);
    }
    if (j < 128) s_h[j] = h0[b * 128 + j];
    __syncthreads();

    float bh = bhh[j];
    for (int t = 0; t < 64; t++) {
        float dt = done[t * 8 + b];
        if (j < 128) s_hm[j] = (1.0f - dt) * s_h[j];
        __syncthreads();
        float acc = bh;
#pragma unroll 8
        for (int k2 = 0; k2 < 64; k2++) {
            float2 wv = __half22float2(s_whh[k2 * 384 + j]);
            float2 hm = *(const float2*)(s_hm + 2 * k2);
            acc = fmaf(hm.x, wv.x, acc);
            acc = fmaf(hm.y, wv.y, acc);
        }
        s_gh[j] = acc;
        __syncthreads();
        if (j < 128) {
            const float* gr = gi + (long)(t * 8 + b) * 384;
            float r = sigf(gr[j] + s_gh[j]);
            float z = sigf(gr[128 + j] + s_gh[128 + j]);
            float nn = tanhf(gr[256 + j] + r * s_gh[256 + j]);
            float hn = (1.0f - z) * nn + z * s_hm[j];
            s_h[j] = hn;
            hidden[(long)(t * 8 + b) * 128 + j] = hn;
        }
        __syncthreads();
    }
}

// ---------------- actor/critic heads ----------------
__global__ void heads_kernel(const float* __restrict__ hidden, const float* __restrict__ aw,
                             const float* __restrict__ ab, const float* __restrict__ cw,
                             const float* __restrict__ cb, float* __restrict__ out) {
    int row = blockIdx.x, t = threadIdx.x;
    __shared__ float s_h[128];
    s_h[t] = hidden[(long)row * 128 + t];
    __syncthreads();
    if (t < 4) {
        const float* w = (t < 3) ? (aw + t * 128) : cw;
        float s = (t < 3) ? ab[t] : cb[0];
        for (int k = 0; k < 128; k++) s = fmaf(s_h[k], w[k], s);
        out[row * 4 + t] = s;
    }
}

// ---------------- host-side launch helpers ----------------
template <int TW, int CIN, int COUT, bool RELU_IN, int MODE, bool RELU_OUT, bool NCHW>
static void launch_fused(const void* in, const __half2* w1, const float* b1,
                         const __half2* w2, const float* b2,
                         void* out, const void* resid, int H, int W) {
    constexpr int CINP = (CIN <= 8) ? 8 : ((CIN <= 16) ? 16 : 32);
    constexpr int PAIRS = CINP / 2;
    constexpr int POP = COUT / 2;
    constexpr int ISTR = (PAIRS == 4) ? 4 : ((PAIRS == 8) ? 12 : 16);
    constexpr int MSTR = (MODE == 0) ? POP : ((POP == 8) ? 12 : 16);
    int smem = (20 * (TW + 4) * ISTR + 18 * (TW + 2) * MSTR) * 4;
    auto kfn = conv_fused_kernel<TW, CIN, COUT, RELU_IN, MODE, RELU_OUT, NCHW>;
    cudaFuncSetAttribute(kfn, cudaFuncAttributeMaxDynamicSharedMemorySize, smem);
    dim3 grid(W / TW, H / 16, 512);
    kfn<<<grid, 256, smem>>>(in, w1, b1, w2, b2, out, resid, H, W);
}

extern "C" void kernel_launch(void* const* d_in, const int* in_sizes, int n_in,
                              void* d_out, int out_size) {
    (void)in_sizes; (void)n_in; (void)out_size;
    const float* x        = (const float*)d_in[0];
    const float* done     = (const float*)d_in[1];
    const float* grustate = (const float*)d_in[2];
    const float* s0_cw = (const float*)d_in[3];
    const float* s0_cb = (const float*)d_in[4];
    const float* s0_rw = (const float*)d_in[5];
    const float* s0_rb = (const float*)d_in[6];
    const float* s1_cw = (const float*)d_in[7];
    const float* s1_cb = (const float*)d_in[8];
    const float* s1_rw = (const float*)d_in[9];
    const float* s1_rb = (const float*)d_in[10];
    const float* s2_cw = (const float*)d_in[11];
    const float* s2_cb = (const float*)d_in[12];
    const float* s2_rw = (const float*)d_in[13];
    const float* s2_rb = (const float*)d_in[14];
    const float* cbam_fc1 = (const float*)d_in[15];
    const float* cbam_fc2 = (const float*)d_in[16];
    const float* cbam_spw = (const float*)d_in[17];
    const float* fc_w  = (const float*)d_in[18];
    const float* fc_b  = (const float*)d_in[19];
    const float* gwih  = (const float*)d_in[20];
    const float* gwhh  = (const float*)d_in[21];
    const float* gbih  = (const float*)d_in[22];
    const float* gbhh  = (const float*)d_in[23];
    const float* aw    = (const float*)d_in[24];
    const float* ab    = (const float*)d_in[25];
    const float* cw    = (const float*)d_in[26];
    const float* cb    = (const float*)d_in[27];
    float* out = (float*)d_out;

    float *X, *O, *FEAT, *GI, *HID, *FCWT;
    __half2* WP;
    cudaGetSymbolAddress((void**)&X, g_X);
    cudaGetSymbolAddress((void**)&O, g_O);
    cudaGetSymbolAddress((void**)&FEAT, g_feat);
    cudaGetSymbolAddress((void**)&GI, g_gi);
    cudaGetSymbolAddress((void**)&HID, g_hid);
    cudaGetSymbolAddress((void**)&FCWT, g_fcwT);
    cudaGetSymbolAddress((void**)&WP, g_wperm2);
    void *Xh = (void*)X, *Oh = (void*)O;

    const int OFF_S0C = 0;
    const int OFF_S0R = 576;
    const int OFF_S1C = 5184;
    const int OFF_S1R = 7488;
    const int OFF_S2C = 25920;
    const int OFF_S2R = 30528;

    wperm_all_kernel<<<(48960 + 255) / 256, 256>>>(s0_cw, s0_rw, s1_cw, s1_rw, s2_cw, s2_rw, WP);
    fcw_permute<<<(256 * 8192 + 255) / 256, 256>>>(fc_w, FCWT);

    // ---- stage 0: head with 32-wide tiles; res TW=16 ----
    launch_fused<32, 6, 16, false, 0, false, true>(x, WP + OFF_S0C, s0_cb, WP + OFF_S0C, s0_cb, Xh, nullptr, 128, 128);
    launch_fused<16, 16, 16, true, 1, false, false>(Xh, WP + OFF_S0R + 0 * 1152, s0_rb + 0,
                                                    WP + OFF_S0R + 1 * 1152, s0_rb + 16, Oh, Xh, 64, 64);
    launch_fused<16, 16, 16, true, 1, false, false>(Oh, WP + OFF_S0R + 2 * 1152, s0_rb + 32,
                                                    WP + OFF_S0R + 3 * 1152, s0_rb + 48, Xh, Oh, 64, 64);

    // ---- stage 1 ----
    launch_fused<16, 16, 32, false, 0, false, false>(Xh, WP + OFF_S1C, s1_cb, WP + OFF_S1C, s1_cb, Oh, nullptr, 64, 64);
    launch_fused<16, 32, 32, true, 1, false, false>(Oh, WP + OFF_S1R + 0 * 4608, s1_rb + 0,
                                                    WP + OFF_S1R + 1 * 4608, s1_rb + 32, Xh, Oh, 32, 32);
    launch_fused<16, 32, 32, true, 1, false, false>(Xh, WP + OFF_S1R + 2 * 4608, s1_rb + 64,
                                                    WP + OFF_S1R + 3 * 4608, s1_rb + 96, Oh, Xh, 32, 32);

    // ---- stage 2 (final res writes fp32 NHWC + relu into X) ----
    launch_fused<16, 32, 32, false, 0, false, false>(Oh, WP + OFF_S2C, s2_cb, WP + OFF_S2C, s2_cb, Xh, nullptr, 32, 32);
    launch_fused<16, 32, 32, true, 1, false, false>(Xh, WP + OFF_S2R + 0 * 4608, s2_rb + 0,
                                                    WP + OFF_S2R + 1 * 4608, s2_rb + 32, Oh, Xh, 16, 16);
    launch_fused<16, 32, 32, true, 2, true, false>(Oh, WP + OFF_S2R + 2 * 4608, s2_rb + 64,
                                                   WP + OFF_S2R + 3 * 4608, s2_rb + 96, (void*)X, Oh, 16, 16);

    // ---- fused CBAM (in place on fp32 X) ----
    cbam_fused_kernel<<<512, 256>>>(X, cbam_fc1, cbam_fc2, cbam_spw);

    // ---- FC + GRU input-gate GEMM (tf32, double-buffered) ----
    gemm_mma_kernel<1><<<dim3(256 / 64, 512 / 32), 256>>>(X, FCWT, fc_b, FEAT, 512, 256, 8192);
    gemm_mma_kernel<0><<<dim3(384 / 64, 512 / 32), 256>>>(FEAT, gwih, gbih, GI, 512, 384, 256);

    // ---- GRU sequential scan ----
    {
        int smem = 64 * 384 * 4 + (384 + 128 + 128) * 4;
        cudaFuncSetAttribute(gru_scan_kernel, cudaFuncAttributeMaxDynamicSharedMemorySize, smem);
        gru_scan_kernel<<<8, 384, smem>>>(GI, done, grustate, gwhh, gbhh, HID);
    }

    // ---- actor / critic heads -> (512, 4) ----
    heads_kernel<<<512, 128>>>(HID, aw, ab, cw, cb, out);
}

// round 15
// speedup vs baseline: 1.2772x; 1.0128x over previous
#include <cuda_runtime.h>
#include <cuda_fp16.h>
#include <math.h>

// ---------------- scratch (device globals; no allocations) ----------------
__device__ float g_X[33554432];
__device__ float g_O[33554432];
__device__ float g_feat[512 * 256];
__device__ float g_gi[512 * 384];
__device__ float g_hid[512 * 128];
__device__ float g_fcwT[256 * 8192];
__device__ __half2 g_wperm2[49152];

__device__ __forceinline__ float sigf(float x) { return 1.0f / (1.0f + expf(-x)); }

__device__ __forceinline__ unsigned tf32u(float x) {
    unsigned r;
    asm("cvt.rna.tf32.f32 %0, %1;" : "=r"(r) : "f"(x));
    return r;
}
__device__ __forceinline__ float tf32f(float x) { return __uint_as_float(tf32u(x)); }

__device__ __forceinline__ void mma8(float* c, unsigned a0, unsigned a1, unsigned a2, unsigned a3,
                                     float b0f, float b1f) {
    unsigned b0 = __float_as_uint(b0f), b1 = __float_as_uint(b1f);
    asm volatile(
        "mma.sync.aligned.m16n8k8.row.col.f32.tf32.tf32.f32 "
        "{%0,%1,%2,%3},{%4,%5,%6,%7},{%8,%9},{%0,%1,%2,%3};"
        : "+f"(c[0]), "+f"(c[1]), "+f"(c[2]), "+f"(c[3])
        : "r"(a0), "r"(a1), "r"(a2), "r"(a3), "r"(b0), "r"(b1));
}
__device__ __forceinline__ void mma16h(float* c, unsigned a0, unsigned a1, unsigned a2, unsigned a3,
                                       unsigned b0, unsigned b1) {
    asm volatile(
        "mma.sync.aligned.m16n8k16.row.col.f32.f16.f16.f32 "
        "{%0,%1,%2,%3},{%4,%5,%6,%7},{%8,%9},{%0,%1,%2,%3};"
        : "+f"(c[0]), "+f"(c[1]), "+f"(c[2]), "+f"(c[3])
        : "r"(a0), "r"(a1), "r"(a2), "r"(a3), "r"(b0), "r"(b1));
}
__device__ __forceinline__ void mma8h(float* c, unsigned a0, unsigned a1, unsigned b0) {
    asm volatile(
        "mma.sync.aligned.m16n8k8.row.col.f32.f16.f16.f32 "
        "{%0,%1,%2,%3},{%4,%5},{%6},{%0,%1,%2,%3};"
        : "+f"(c[0]), "+f"(c[1]), "+f"(c[2]), "+f"(c[3])
        : "r"(a0), "r"(a1), "r"(b0));
}
__device__ __forceinline__ void ldsm_x4(unsigned& r0, unsigned& r1, unsigned& r2, unsigned& r3,
                                        unsigned addr) {
    asm volatile("ldmatrix.sync.aligned.m8n8.x4.shared.b16 {%0,%1,%2,%3}, [%4];"
                 : "=r"(r0), "=r"(r1), "=r"(r2), "=r"(r3) : "r"(addr));
}
__device__ __forceinline__ void ldsm_x2(unsigned& r0, unsigned& r1, unsigned addr) {
    asm volatile("ldmatrix.sync.aligned.m8n8.x2.shared.b16 {%0,%1}, [%2];"
                 : "=r"(r0), "=r"(r1) : "r"(addr));
}
#define U(x) __float_as_uint(x)

__device__ __forceinline__ int pslot(int p, int PAIRS) {
    if (PAIRS == 4)  return p;
    if (PAIRS == 8)  return 2 * (p & 3) + (p >> 2);
    return 4 * (p & 3) + (p >> 2);
}
__device__ __forceinline__ unsigned packh2(float a, float b) {
    __half2 h = __floats2half2_rn(a, b);
    return *(unsigned*)&h;
}
__device__ __forceinline__ unsigned relu_u(unsigned u) {
    __half2 h = *(__half2*)&u;
    h = __hmax2(h, __half2half2(__float2half(0.0f)));
    return *(unsigned*)&h;
}
__device__ __forceinline__ uint4 relu4(uint4 v) {
    v.x = relu_u(v.x); v.y = relu_u(v.y); v.z = relu_u(v.z); v.w = relu_u(v.w);
    return v;
}

// ---------------- weight permute prepass -> fp16 pairs [tap][co][pslot] ----
__global__ void wperm_all_kernel(const float* __restrict__ s0c, const float* __restrict__ s0r,
                                 const float* __restrict__ s1c, const float* __restrict__ s1r,
                                 const float* __restrict__ s2c, const float* __restrict__ s2r,
                                 __half2* __restrict__ dst) {
    int i = blockIdx.x * 256 + threadIdx.x;
    if (i >= 48960) return;
    const float* src; int CIN, PAIRS, COUT, base;
    if (i < 576)        { src = s0c; CIN = 6;  PAIRS = 4;  COUT = 16; base = 0; }
    else if (i < 5184)  { src = s0r; CIN = 16; PAIRS = 8;  COUT = 16; base = 576; }
    else if (i < 7488)  { src = s1c; CIN = 16; PAIRS = 8;  COUT = 32; base = 5184; }
    else if (i < 25920) { src = s1r; CIN = 32; PAIRS = 16; COUT = 32; base = 7488; }
    else if (i < 30528) { src = s2c; CIN = 32; PAIRS = 16; COUT = 32; base = 25920; }
    else                { src = s2r; CIN = 32; PAIRS = 16; COUT = 32; base = 30528; }
    int li = i - base;
    int tap = li % 9; int r = li / 9;
    int p = r % PAIRS; r /= PAIRS;
    int co = r % COUT; int cv = r / COUT;
    int ci0 = 2 * p, ci1 = 2 * p + 1;
    float v0 = (ci0 < CIN) ? src[((cv * COUT + co) * CIN + ci0) * 9 + tap] : 0.0f;
    float v1 = (ci1 < CIN) ? src[((cv * COUT + co) * CIN + ci1) * 9 + tap] : 0.0f;
    dst[base + cv * 9 * COUT * PAIRS + (tap * COUT + co) * PAIRS + pslot(p, PAIRS)] =
        __floats2half2_rn(v0, v1);
}

// permute fc_w[n][c*256+p] -> g_fcwT[n][p*32+c]
__global__ void fcw_permute(const float* __restrict__ w, float* __restrict__ wt) {
    int i = blockIdx.x * 256 + threadIdx.x;
    if (i >= 256 * 8192) return;
    int n = i >> 13;
    int r = i & 8191;
    int c = r >> 8, p = r & 255;
    wt[(n << 13) + p * 32 + c] = w[i];
}

// ---------------- fused conv kernel (TW = tile width, height 16) -----------
// MODE 0: conv -> maxpool -> fp16 out.  MODE 1: resblock fp16 out.  MODE 2: fp32 NHWC out.
// MINB: blocks/SM bound (controls register budget; avoid spills on big-acc variants)
template <int TW, int CIN, int COUT, bool RELU_IN, int MODE, bool RELU_OUT, bool NCHW, int MINB>
__global__ __launch_bounds__(256, MINB) void conv_fused_kernel(
    const void* __restrict__ in, const __half2* __restrict__ w1,
    const float* __restrict__ b1v, const __half2* __restrict__ w2,
    const float* __restrict__ b2v, void* __restrict__ out,
    const void* __restrict__ resid, int H, int W) {
    constexpr int CINP = (CIN <= 8) ? 8 : ((CIN <= 16) ? 16 : 32);
    constexpr int PAIRS = CINP / 2;
    constexpr int POP = COUT / 2;
    constexpr int NB = COUT / 8;
    constexpr int HW = TW + 4;
    constexpr int RW = TW + 2;
    constexpr int HPIX = 20 * HW;
    constexpr int NPIX = 18 * RW;
    constexpr int NSUB = (NPIX + 127) / 128;
    constexpr int ISTR = (PAIRS == 4) ? 4 : ((PAIRS == 8) ? 12 : 16);
    constexpr int IN_W = HPIX * ISTR;
    constexpr int MSTR = (MODE == 0) ? POP : ((POP == 8) ? 12 : 16);
    constexpr int MID_W = NPIX * MSTR;

    extern __shared__ __half2 smh[];
    __half2* s_in2 = smh;
    __half2* s_mid2 = smh + IN_W;

    const int tid = threadIdx.x;
    const int n = blockIdx.z;
    const int by = blockIdx.y * 16, bx = blockIdx.x * TW;
    const unsigned sb_in = (unsigned)__cvta_generic_to_shared(s_in2);
    const unsigned sb_mid = (unsigned)__cvta_generic_to_shared(s_mid2);

    for (int i = tid; i < MID_W; i += 256) ((unsigned*)s_mid2)[i] = 0u;

    // ---- stage halo (20 x HW) ----
    for (int p = tid; p < HPIX; p += 256) {
        int iy = p / HW, ix = p - iy * HW;
        int gy = by + iy - 2, gx = bx + ix - 2;
        bool ok = (gy >= 0 && gy < H && gx >= 0 && gx < W);
        if (NCHW) {
            const float* inf = (const float*)in;
            uint4 wv = make_uint4(0u, 0u, 0u, 0u);
            if (ok) {
                long base = ((long)n * CIN * H + gy) * W + gx;
                long st = (long)H * W;
                wv = make_uint4(packh2(inf[base], inf[base + st]),
                                packh2(inf[base + 2 * st], inf[base + 3 * st]),
                                packh2(inf[base + 4 * st], inf[base + 5 * st]), 0u);
            }
            *(uint4*)(s_in2 + p * 4) = wv;
        } else if (PAIRS == 8) {
            uint4 lo = make_uint4(0u, 0u, 0u, 0u), hi = lo;
            if (ok) {
                const uint4* gp = (const uint4*)((const __half2*)in + ((long)(n * H + gy) * W + gx) * 8);
                lo = gp[0]; hi = gp[1];
                if (RELU_IN) { lo = relu4(lo); hi = relu4(hi); }
            }
            *(uint4*)(s_in2 + p * 12) = lo;
            *(uint4*)(s_in2 + p * 12 + 4) = hi;
        } else {
            uint4 v0 = make_uint4(0,0,0,0), v1 = v0, v2 = v0, v3 = v0;
            if (ok) {
                const uint4* gp = (const uint4*)((const __half2*)in + ((long)(n * H + gy) * W + gx) * 16);
                v0 = gp[0]; v1 = gp[1]; v2 = gp[2]; v3 = gp[3];
                if (RELU_IN) { v0 = relu4(v0); v1 = relu4(v1); v2 = relu4(v2); v3 = relu4(v3); }
            }
            *(uint4*)(s_in2 + p * 16) = v0;
            *(uint4*)(s_in2 + p * 16 + 4) = v1;
            *(uint4*)(s_in2 + p * 16 + 8) = v2;
            *(uint4*)(s_in2 + p * 16 + 12) = v3;
        }
    }
    __syncthreads();

    const int warp = tid >> 5, lane = tid & 31, g = lane >> 2, t = lane & 3;
    const char* suc = (const char*)s_in2;
    const char* w1c = (const char*)w1;

    float acc1[NSUB][NB][4];
#pragma unroll
    for (int s = 0; s < NSUB; s++)
#pragma unroll
        for (int nb = 0; nb < NB; nb++)
#pragma unroll
            for (int q = 0; q < 4; q++) acc1[s][nb][q] = 0.0f;

    unsigned lmaddr[NSUB];
    const char* a0p[NSUB]; const char* a1p[NSUB];
    if (PAIRS == 4 || PAIRS == 8) {
        int i8 = lane & 7, mm = lane >> 3;
#pragma unroll
        for (int s = 0; s < NSUB; s++) {
            int tt = warp + 8 * s;
            int p = tt * 16 + i8 + (mm & 1) * 8;
            if (p > NPIX - 1) p = NPIX - 1;
            int pix = (p / RW + 1) * HW + (p % RW) + 1;
            if (PAIRS == 4) lmaddr[s] = sb_in + pix * 16;
            else            lmaddr[s] = sb_in + pix * 48 + (mm >> 1) * 16;
        }
    } else {
#pragma unroll
        for (int s = 0; s < NSUB; s++) {
            int tt = warp + 8 * s;
            int p0 = tt * 16 + g, p1 = p0 + 8;
            int q0 = p0 > NPIX - 1 ? NPIX - 1 : p0, q1 = p1 > NPIX - 1 ? NPIX - 1 : p1;
            int b0 = (q0 / RW + 1) * HW + (q0 % RW + 1);
            int b1 = (q1 / RW + 1) * HW + (q1 % RW + 1);
            a0p[s] = suc + b0 * 64 + t * 16;
            a1p[s] = suc + b1 * 64 + t * 16;
        }
    }
    const char* wp1[NB];
#pragma unroll
    for (int nb = 0; nb < NB; nb++) {
        int co = nb * 8 + g;
        if (PAIRS == 4)      wp1[nb] = w1c + co * 16 + t * 4;
        else if (PAIRS == 8) wp1[nb] = w1c + co * 32 + t * 8;
        else                 wp1[nb] = w1c + co * 64 + t * 16;
    }

#pragma unroll
    for (int tap = 0; tap < 9; tap++) {
        const int dy = tap / 3 - 1, dx = tap % 3 - 1;
        const int off = dy * HW + dx;
        if (PAIRS == 4) {
            const int wimm = tap * COUT * 16;
            unsigned vb[NB];
#pragma unroll
            for (int nb = 0; nb < NB; nb++) vb[nb] = *(const unsigned*)(wp1[nb] + wimm);
#pragma unroll
            for (int s = 0; s < NSUB; s++) {
                unsigned a0, a1;
                ldsm_x2(a0, a1, lmaddr[s] + off * 16);
#pragma unroll
                for (int nb = 0; nb < NB; nb++) mma8h(acc1[s][nb], a0, a1, vb[nb]);
            }
        } else if (PAIRS == 8) {
            const int wimm = tap * COUT * 32;
            uint2 vb[NB];
#pragma unroll
            for (int nb = 0; nb < NB; nb++) vb[nb] = *(const uint2*)(wp1[nb] + wimm);
#pragma unroll
            for (int s = 0; s < NSUB; s++) {
                unsigned a0, a1, a2, a3;
                ldsm_x4(a0, a1, a2, a3, lmaddr[s] + off * 48);
#pragma unroll
                for (int nb = 0; nb < NB; nb++)
                    mma16h(acc1[s][nb], a0, a1, a2, a3, vb[nb].x, vb[nb].y);
            }
        } else {
            const int wimm = tap * COUT * 64, aimm = off * 64;
            uint4 vb[NB];
#pragma unroll
            for (int nb = 0; nb < NB; nb++) vb[nb] = *(const uint4*)(wp1[nb] + wimm);
#pragma unroll
            for (int s = 0; s < NSUB; s++) {
                uint4 va0 = *(const uint4*)(a0p[s] + aimm);
                uint4 va1 = *(const uint4*)(a1p[s] + aimm);
#pragma unroll
                for (int nb = 0; nb < NB; nb++) {
                    mma16h(acc1[s][nb], va0.x, va1.x, va0.y, va1.y, vb[nb].x, vb[nb].y);
                    mma16h(acc1[s][nb], va0.z, va1.z, va0.w, va1.w, vb[nb].z, vb[nb].w);
                }
            }
        }
    }

    // ---- store conv1 results to mid ----
#pragma unroll
    for (int s = 0; s < NSUB; s++) {
        int pbase = (warp + 8 * s) * 16 + g;
#pragma unroll
        for (int half = 0; half < 2; half++) {
            int p = pbase + 8 * half;
            if (p < NPIX) {
                int r = p / RW, c = p - r * RW;
                int gy = by - 1 + r, gx = bx - 1 + c;
                if (gy >= 0 && gy < H && gx >= 0 && gx < W) {
#pragma unroll
                    for (int nb = 0; nb < NB; nb++) {
                        int co = nb * 8 + 2 * t;
                        int pr = nb * 4 + t;
                        float v0 = acc1[s][nb][2 * half + 0] + b1v[co];
                        float v1 = acc1[s][nb][2 * half + 1] + b1v[co + 1];
                        if (MODE == 0) {
                            s_mid2[p * POP + pr] = __floats2half2_rn(v0, v1);
                        } else if (POP == 8) {
                            s_mid2[p * 12 + pr] =
                                __floats2half2_rn(fmaxf(v0, 0.0f), fmaxf(v1, 0.0f));
                        } else {
                            s_mid2[p * 16 + (pslot(pr, 16) ^ ((p & 1) << 3))] =
                                __floats2half2_rn(fmaxf(v0, 0.0f), fmaxf(v1, 0.0f));
                        }
                    }
                }
            }
        }
    }
    __syncthreads();

    if (MODE == 0) {
        int H2 = H >> 1, W2 = W >> 1;
        __half2* outh = (__half2*)out;
        for (int o = tid; o < 4 * TW * POP; o += 256) {
            int pr = o % POP; int pp = o / POP;
            int ly = pp / (TW / 2), lx = pp % (TW / 2);
            __half2 m = __floats2half2_rn(-65504.0f, -65504.0f);
#pragma unroll
            for (int dy = 0; dy < 3; dy++) {
                int r = 2 * ly + dy;
                int gy = by - 1 + r;
                if (gy < 0 || gy >= H) continue;
#pragma unroll
                for (int dxx = 0; dxx < 3; dxx++) {
                    int c = 2 * lx + dxx;
                    int gx = bx - 1 + c;
                    if (gx < 0 || gx >= W) continue;
                    m = __hmax2(m, s_mid2[(r * RW + c) * POP + pr]);
                }
            }
            long op = ((long)n * H2 + (by / 2 + ly)) * W2 + (bx / 2 + lx);
            outh[op * POP + (COUT == 16 ? pr : pslot(pr, 16))] = m;
        }
    } else {
        const char* muc = (const char*)s_mid2;
        const char* w2c = (const char*)w2;
        const int wr0 = warp * 2;
        float acc[2][NB][4];
#pragma unroll
        for (int r = 0; r < 2; r++)
#pragma unroll
            for (int nb = 0; nb < NB; nb++)
#pragma unroll
                for (int q = 0; q < 4; q++) acc[r][nb][q] = 0.0f;

        unsigned m_lm[2];
        if (POP == 8) {
            int i8 = lane & 7, mm = lane >> 3;
#pragma unroll
            for (int r = 0; r < 2; r++) {
                int pix = (wr0 + r + 1) * RW + 1 + i8 + (mm & 1) * 8;
                m_lm[r] = sb_mid + pix * 48 + (mm >> 1) * 16;
            }
        }
        const char* wp2[NB];
#pragma unroll
        for (int nb = 0; nb < NB; nb++) {
            int co = nb * 8 + g;
            wp2[nb] = (POP == 8) ? (w2c + co * 32 + t * 8) : (w2c + co * 64 + t * 16);
        }

#pragma unroll
        for (int tap = 0; tap < 9; tap++) {
            const int dy = tap / 3 - 1, dx = tap % 3 - 1;
            const int off = dy * RW + dx;
            if (POP == 8) {
                const int wimm = tap * COUT * 32;
                uint2 vb[NB];
#pragma unroll
                for (int nb = 0; nb < NB; nb++) vb[nb] = *(const uint2*)(wp2[nb] + wimm);
#pragma unroll
                for (int r = 0; r < 2; r++) {
                    unsigned a0, a1, a2, a3;
                    ldsm_x4(a0, a1, a2, a3, m_lm[r] + off * 48);
#pragma unroll
                    for (int nb = 0; nb < NB; nb++)
                        mma16h(acc[r][nb], a0, a1, a2, a3, vb[nb].x, vb[nb].y);
                }
            } else {
                const int wimm = tap * COUT * 64;
                uint4 vb[NB];
#pragma unroll
                for (int nb = 0; nb < NB; nb++) vb[nb] = *(const uint4*)(wp2[nb] + wimm);
#pragma unroll
                for (int r = 0; r < 2; r++) {
                    int pb0 = (wr0 + r + dy + 1) * RW + dx + 1 + g;
                    int pb1 = pb0 + 8;
                    const char* q0 = muc + pb0 * 64 + (t * 16 ^ ((pb0 & 1) << 5));
                    const char* q1 = muc + pb1 * 64 + (t * 16 ^ ((pb1 & 1) << 5));
                    uint4 va0 = *(const uint4*)q0;
                    uint4 va1 = *(const uint4*)q1;
#pragma unroll
                    for (int nb = 0; nb < NB; nb++) {
                        mma16h(acc[r][nb], va0.x, va1.x, va0.y, va1.y, vb[nb].x, vb[nb].y);
                        mma16h(acc[r][nb], va0.z, va1.z, va0.w, va1.w, vb[nb].z, vb[nb].w);
                    }
                }
            }
        }

        const __half2* res2 = (const __half2*)resid;
#pragma unroll
        for (int r = 0; r < 2; r++) {
            int oy = by + wr0 + r;
            long oprow = (long)(n * H + oy) * W + bx;
#pragma unroll
            for (int nb = 0; nb < NB; nb++) {
                int pr = nb * 4 + t;
                int sl = (POP == 8) ? pr : pslot(pr, 16);
                int co = 2 * pr;
                float bv0 = b2v[co], bv1 = b2v[co + 1];
                long i0 = (oprow + g) * POP + sl;
                long i1 = (oprow + g + 8) * POP + sl;
                float2 r0 = __half22float2(res2[i0]);
                float2 r1 = __half22float2(res2[i1]);
                float v00 = acc[r][nb][0] + bv0 + r0.x, v01 = acc[r][nb][1] + bv1 + r0.y;
                float v10 = acc[r][nb][2] + bv0 + r1.x, v11 = acc[r][nb][3] + bv1 + r1.y;
                if (RELU_OUT) {
                    v00 = fmaxf(v00, 0.0f); v01 = fmaxf(v01, 0.0f);
                    v10 = fmaxf(v10, 0.0f); v11 = fmaxf(v11, 0.0f);
                }
                if (MODE == 1) {
                    __half2* outh = (__half2*)out;
                    outh[i0] = __floats2half2_rn(v00, v01);
                    outh[i1] = __floats2half2_rn(v10, v11);
                } else {
                    float* outf = (float*)out;
                    *(float2*)(outf + (oprow + g) * COUT + co) = make_float2(v00, v01);
                    *(float2*)(outf + (oprow + g + 8) * COUT + co) = make_float2(v10, v11);
                }
            }
        }
    }
}

// ---------------- fused CBAM (fp32 NHWC X, in place) ----------------
__global__ __launch_bounds__(256) void cbam_fused_kernel(
    float* __restrict__ x, const float* __restrict__ fc1, const float* __restrict__ fc2,
    const float* __restrict__ spw) {
    __shared__ float s_x[256 * 36];
    __shared__ float rs[8][32], rm[8][32];
    __shared__ float s_mean[32], s_max[32], s_h[8], s_ca[32], s_sp[512], s_w[98];
    const int n = blockIdx.x, tid = threadIdx.x;

    float* gbase = x + ((long)n * 256 + tid) * 32;
#pragma unroll
    for (int c = 0; c < 32; c += 4)
        *(float4*)(s_x + tid * 36 + c) = *(const float4*)(gbase + c);
    if (tid < 98) s_w[tid] = spw[tid];
    __syncthreads();

    {
        int g = tid >> 5, c = tid & 31;
        float sm = 0.0f, mx = -3.4e38f;
        for (int p = g; p < 256; p += 8) {
            float v = s_x[p * 36 + c];
            sm += v; mx = fmaxf(mx, v);
        }
        rs[g][c] = sm; rm[g][c] = mx;
    }
    __syncthreads();
    if (tid < 32) {
        float s = 0.0f, m = -3.4e38f;
        for (int q = 0; q < 8; q++) { s += rs[q][tid]; m = fmaxf(m, rm[q][tid]); }
        s_mean[tid] = s * (1.0f / 256.0f); s_max[tid] = m;
    }
    __syncthreads();
    if (tid < 8) {
        float hm = 0.0f, hx = 0.0f;
        for (int k = 0; k < 32; k++) {
            float wv = fc1[tid * 32 + k];
            hm += s_mean[k] * wv; hx += s_max[k] * wv;
        }
        s_h[tid] = fmaxf(hm, 0.0f) + fmaxf(hx, 0.0f);
    }
    __syncthreads();
    if (tid < 32) {
        float o = 0.0f;
        for (int j = 0; j < 8; j++) o += s_h[j] * fc2[tid * 8 + j];
        s_ca[tid] = sigf(o);
    }
    __syncthreads();

    {
        float sum = 0.0f, mx = -3.4e38f;
#pragma unroll
        for (int c = 0; c < 32; c++) {
            float v = s_x[tid * 36 + c] * s_ca[c];
            s_x[tid * 36 + c] = v;
            sum += v; mx = fmaxf(mx, v);
        }
        s_sp[tid] = sum * (1.0f / 32.0f);
        s_sp[256 + tid] = mx;
    }
    __syncthreads();

    {
        int oy = tid >> 4, ox = tid & 15;
        float a = 0.0f;
#pragma unroll
        for (int ci = 0; ci < 2; ci++)
            for (int ky = 0; ky < 7; ky++) {
                int y = oy + ky - 3;
                if (y < 0 || y >= 16) continue;
                for (int kx = 0; kx < 7; kx++) {
                    int xx = ox + kx - 3;
                    if (xx < 0 || xx >= 16) continue;
                    a = fmaf(s_sp[ci * 256 + y * 16 + xx], s_w[(ci * 7 + ky) * 7 + kx], a);
                }
            }
        float sa = sigf(a);
#pragma unroll
        for (int c = 0; c < 32; c += 4) {
            float4 v;
            v.x = s_x[tid * 36 + c] * sa;
            v.y = s_x[tid * 36 + c + 1] * sa;
            v.z = s_x[tid * 36 + c + 2] * sa;
            v.w = s_x[tid * 36 + c + 3] * sa;
            *(float4*)(gbase + c) = v;
        }
    }
}

// ---------------- tf32 MMA GEMM, single-sync double-buffered --------------
template <int RELU>
__global__ __launch_bounds__(256) void gemm_mma_kernel(
    const float* __restrict__ A, const float* __restrict__ B,
    const float* __restrict__ bias, float* __restrict__ C,
    int M, int N, int K) {
    __shared__ float sA[2][32 * 36], sB[2][64 * 36];
    const int tid = threadIdx.x;
    const int bm = blockIdx.y * 32, bn = blockIdx.x * 64;
    const int warp = tid >> 5, lane = tid & 31, g = lane >> 2, t = lane & 3;
    const int wm = warp >> 2, wn = warp & 3;
    const int lrA = tid >> 3, lcA = (tid & 7) * 4;
    const int lrB = tid >> 2, lcB = (tid & 3) * 8;

    float acc[2][4];
#pragma unroll
    for (int i = 0; i < 2; i++)
#pragma unroll
        for (int q = 0; q < 4; q++) acc[i][q] = 0.0f;

    const float* pA = A + (long)(bm + lrA) * K + lcA;
    const float* pB = B + (long)(bn + lrB) * K + lcB;

    float4 va = *(const float4*)(pA);
    float4 vb0 = *(const float4*)(pB);
    float4 vb1 = *(const float4*)(pB + 4);
    {
        float* pa = sA[0] + lrA * 36 + lcA;
        float* pb = sB[0] + lrB * 36 + lcB;
        pa[0]=tf32f(va.x); pa[1]=tf32f(va.y); pa[2]=tf32f(va.z); pa[3]=tf32f(va.w);
        pb[0]=tf32f(vb0.x); pb[1]=tf32f(vb0.y); pb[2]=tf32f(vb0.z); pb[3]=tf32f(vb0.w);
        pb[4]=tf32f(vb1.x); pb[5]=tf32f(vb1.y); pb[6]=tf32f(vb1.z); pb[7]=tf32f(vb1.w);
    }
    __syncthreads();

    int buf = 0;
    for (int k0 = 0; k0 < K; k0 += 32) {
        bool has_next = (k0 + 32 < K);
        if (has_next) {
            va = *(const float4*)(pA + k0 + 32);
            vb0 = *(const float4*)(pB + k0 + 32);
            vb1 = *(const float4*)(pB + k0 + 36);
        }
        const float* cA = sA[buf];
        const float* cB = sB[buf];
#pragma unroll
        for (int ks = 0; ks < 4; ks++) {
            const int k = ks * 8;
            const int r0 = wm * 16 + g;
            unsigned a0 = U(cA[r0 * 36 + k + t]),     a1 = U(cA[(r0 + 8) * 36 + k + t]);
            unsigned a2 = U(cA[r0 * 36 + k + t + 4]), a3 = U(cA[(r0 + 8) * 36 + k + t + 4]);
#pragma unroll
            for (int nt = 0; nt < 2; nt++) {
                int nr = wn * 16 + nt * 8 + g;
                mma8(acc[nt], a0, a1, a2, a3, cB[nr * 36 + k + t], cB[nr * 36 + k + t + 4]);
            }
        }
        if (has_next) {
            float* pa = sA[buf ^ 1] + lrA * 36 + lcA;
            float* pb = sB[buf ^ 1] + lrB * 36 + lcB;
            pa[0]=tf32f(va.x); pa[1]=tf32f(va.y); pa[2]=tf32f(va.z); pa[3]=tf32f(va.w);
            pb[0]=tf32f(vb0.x); pb[1]=tf32f(vb0.y); pb[2]=tf32f(vb0.z); pb[3]=tf32f(vb0.w);
            pb[4]=tf32f(vb1.x); pb[5]=tf32f(vb1.y); pb[6]=tf32f(vb1.z); pb[7]=tf32f(vb1.w);
        }
        __syncthreads();
        buf ^= 1;
    }
#pragma unroll
    for (int nt = 0; nt < 2; nt++) {
        int n0 = bn + wn * 16 + nt * 8 + 2 * t;
        int m0 = bm + wm * 16 + g;
        float b0 = bias[n0], b1 = bias[n0 + 1];
        float v00 = acc[nt][0] + b0, v01 = acc[nt][1] + b1;
        float v10 = acc[nt][2] + b0, v11 = acc[nt][3] + b1;
        if (RELU) {
            v00 = fmaxf(v00, 0.0f); v01 = fmaxf(v01, 0.0f);
            v10 = fmaxf(v10, 0.0f); v11 = fmaxf(v11, 0.0f);
        }
        C[(long)m0 * N + n0] = v00;       C[(long)m0 * N + n0 + 1] = v01;
        C[(long)(m0 + 8) * N + n0] = v10; C[(long)(m0 + 8) * N + n0 + 1] = v11;
    }
}

// ---------------- GRU scan (whh as fp16 pairs in smem) ----------------
__global__ void gru_scan_kernel(const float* __restrict__ gi, const float* __restrict__ done,
                                const float* __restrict__ h0, const float* __restrict__ whh,
                                const float* __restrict__ bhh, float* __restrict__ hidden) {
    extern __shared__ __half2 smg[];
    __half2* s_whh = smg;
    float* s_gh = (float*)(smg + 64 * 384);
    float* s_h = s_gh + 384;
    float* s_hm = s_h + 128;
    int b = blockIdx.x, j = threadIdx.x;

    for (int i = j; i < 64 * 384; i += 384) {
        int jj = i / 64, k2 = i - jj * 64;
        s_whh[k2 * 384 + jj] = __floats2half2_rn(whh[jj * 128 + 2 * k2],
                                                 whh[jj * 128 + 2 * k2 + 1]);
    }
    if (j < 128) s_h[j] = h0[b * 128 + j];
    __syncthreads();

    float bh = bhh[j];
    for (int t = 0; t < 64; t++) {
        float dt = done[t * 8 + b];
        if (j < 128) s_hm[j] = (1.0f - dt) * s_h[j];
        __syncthreads();
        float acc = bh;
#pragma unroll 8
        for (int k2 = 0; k2 < 64; k2++) {
            float2 wv = __half22float2(s_whh[k2 * 384 + j]);
            float2 hm = *(const float2*)(s_hm + 2 * k2);
            acc = fmaf(hm.x, wv.x, acc);
            acc = fmaf(hm.y, wv.y, acc);
        }
        s_gh[j] = acc;
        __syncthreads();
        if (j < 128) {
            const float* gr = gi + (long)(t * 8 + b) * 384;
            float r = sigf(gr[j] + s_gh[j]);
            float z = sigf(gr[128 + j] + s_gh[128 + j]);
            float nn = tanhf(gr[256 + j] + r * s_gh[256 + j]);
            float hn = (1.0f - z) * nn + z * s_hm[j];
            s_h[j] = hn;
            hidden[(long)(t * 8 + b) * 128 + j] = hn;
        }
        __syncthreads();
    }
}

// ---------------- actor/critic heads ----------------
__global__ void heads_kernel(const float* __restrict__ hidden, const float* __restrict__ aw,
                             const float* __restrict__ ab, const float* __restrict__ cw,
                             const float* __restrict__ cb, float* __restrict__ out) {
    int row = blockIdx.x, t = threadIdx.x;
    __shared__ float s_h[128];
    s_h[t] = hidden[(long)row * 128 + t];
    __syncthreads();
    if (t < 4) {
        const float* w = (t < 3) ? (aw + t * 128) : cw;
        float s = (t < 3) ? ab[t] : cb[0];
        for (int k = 0; k < 128; k++) s = fmaf(s_h[k], w[k], s);
        out[row * 4 + t] = s;
    }
}

// ---------------- host-side launch helpers ----------------
template <int TW, int CIN, int COUT, bool RELU_IN, int MODE, bool RELU_OUT, bool NCHW, int MINB>
static void launch_fused(const void* in, const __half2* w1, const float* b1,
                         const __half2* w2, const float* b2,
                         void* out, const void* resid, int H, int W) {
    constexpr int CINP = (CIN <= 8) ? 8 : ((CIN <= 16) ? 16 : 32);
    constexpr int PAIRS = CINP / 2;
    constexpr int POP = COUT / 2;
    constexpr int ISTR = (PAIRS == 4) ? 4 : ((PAIRS == 8) ? 12 : 16);
    constexpr int MSTR = (MODE == 0) ? POP : ((POP == 8) ? 12 : 16);
    int smem = (20 * (TW + 4) * ISTR + 18 * (TW + 2) * MSTR) * 4;
    auto kfn = conv_fused_kernel<TW, CIN, COUT, RELU_IN, MODE, RELU_OUT, NCHW, MINB>;
    cudaFuncSetAttribute(kfn, cudaFuncAttributeMaxDynamicSharedMemorySize, smem);
    dim3 grid(W / TW, H / 16, 512);
    kfn<<<grid, 256, smem>>>(in, w1, b1, w2, b2, out, resid, H, W);
}

extern "C" void kernel_launch(void* const* d_in, const int* in_sizes, int n_in,
                              void* d_out, int out_size) {
    (void)in_sizes; (void)n_in; (void)out_size;
    const float* x        = (const float*)d_in[0];
    const float* done     = (const float*)d_in[1];
    const float* grustate = (const float*)d_in[2];
    const float* s0_cw = (const float*)d_in[3];
    const float* s0_cb = (const float*)d_in[4];
    const float* s0_rw = (const float*)d_in[5];
    const float* s0_rb = (const float*)d_in[6];
    const float* s1_cw = (const float*)d_in[7];
    const float* s1_cb = (const float*)d_in[8];
    const float* s1_rw = (const float*)d_in[9];
    const float* s1_rb = (const float*)d_in[10];
    const float* s2_cw = (const float*)d_in[11];
    const float* s2_cb = (const float*)d_in[12];
    const float* s2_rw = (const float*)d_in[13];
    const float* s2_rb = (const float*)d_in[14];
    const float* cbam_fc1 = (const float*)d_in[15];
    const float* cbam_fc2 = (const float*)d_in[16];
    const float* cbam_spw = (const float*)d_in[17];
    const float* fc_w  = (const float*)d_in[18];
    const float* fc_b  = (const float*)d_in[19];
    const float* gwih  = (const float*)d_in[20];
    const float* gwhh  = (const float*)d_in[21];
    const float* gbih  = (const float*)d_in[22];
    const float* gbhh  = (const float*)d_in[23];
    const float* aw    = (const float*)d_in[24];
    const float* ab    = (const float*)d_in[25];
    const float* cw    = (const float*)d_in[26];
    const float* cb    = (const float*)d_in[27];
    float* out = (float*)d_out;

    float *X, *O, *FEAT, *GI, *HID, *FCWT;
    __half2* WP;
    cudaGetSymbolAddress((void**)&X, g_X);
    cudaGetSymbolAddress((void**)&O, g_O);
    cudaGetSymbolAddress((void**)&FEAT, g_feat);
    cudaGetSymbolAddress((void**)&GI, g_gi);
    cudaGetSymbolAddress((void**)&HID, g_hid);
    cudaGetSymbolAddress((void**)&FCWT, g_fcwT);
    cudaGetSymbolAddress((void**)&WP, g_wperm2);
    void *Xh = (void*)X, *Oh = (void*)O;

    const int OFF_S0C = 0;
    const int OFF_S0R = 576;
    const int OFF_S1C = 5184;
    const int OFF_S1R = 7488;
    const int OFF_S2C = 25920;
    const int OFF_S2R = 30528;

    wperm_all_kernel<<<(48960 + 255) / 256, 256>>>(s0_cw, s0_rw, s1_cw, s1_rw, s2_cw, s2_rw, WP);
    fcw_permute<<<(256 * 8192 + 255) / 256, 256>>>(fc_w, FCWT);

    // ---- stage 0: head TW32 MINB3 (NSUB5, big acc); res TW16 MINB4 ----
    launch_fused<32, 6, 16, false, 0, false, true, 3>(x, WP + OFF_S0C, s0_cb, WP + OFF_S0C, s0_cb, Xh, nullptr, 128, 128);
    launch_fused<16, 16, 16, true, 1, false, false, 4>(Xh, WP + OFF_S0R + 0 * 1152, s0_rb + 0,
                                                       WP + OFF_S0R + 1 * 1152, s0_rb + 16, Oh, Xh, 64, 64);
    launch_fused<16, 16, 16, true, 1, false, false, 4>(Oh, WP + OFF_S0R + 2 * 1152, s0_rb + 32,
                                                       WP + OFF_S0R + 3 * 1152, s0_rb + 48, Xh, Oh, 64, 64);

    // ---- stage 1: head COUT32 (acc 48) MINB3; res CIN32 MINB3 ----
    launch_fused<16, 16, 32, false, 0, false, false, 3>(Xh, WP + OFF_S1C, s1_cb, WP + OFF_S1C, s1_cb, Oh, nullptr, 64, 64);
    launch_fused<16, 32, 32, true, 1, false, false, 3>(Oh, WP + OFF_S1R + 0 * 4608, s1_rb + 0,
                                                       WP + OFF_S1R + 1 * 4608, s1_rb + 32, Xh, Oh, 32, 32);
    launch_fused<16, 32, 32, true, 1, false, false, 3>(Xh, WP + OFF_S1R + 2 * 4608, s1_rb + 64,
                                                       WP + OFF_S1R + 3 * 4608, s1_rb + 96, Oh, Xh, 32, 32);

    // ---- stage 2 (final res writes fp32 NHWC + relu into X) ----
    launch_fused<16, 32, 32, false, 0, false, false, 3>(Oh, WP + OFF_S2C, s2_cb, WP + OFF_S2C, s2_cb, Xh, nullptr, 32, 32);
    launch_fused<16, 32, 32, true, 1, false, false, 3>(Xh, WP + OFF_S2R + 0 * 4608, s2_rb + 0,
                                                       WP + OFF_S2R + 1 * 4608, s2_rb + 32, Oh, Xh, 16, 16);
    launch_fused<16, 32, 32, true, 2, true, false, 3>(Oh, WP + OFF_S2R + 2 * 4608, s2_rb + 64,
                                                      WP + OFF_S2R + 3 * 4608, s2_rb + 96, (void*)X, Oh, 16, 16);

    // ---- fused CBAM (in place on fp32 X) ----
    cbam_fused_kernel<<<512, 256>>>(X, cbam_fc1, cbam_fc2, cbam_spw);

    // ---- FC + GRU input-gate GEMM (tf32, double-buffered) ----
    gemm_mma_kernel<1><<<dim3(256 / 64, 512 / 32), 256>>>(X, FCWT, fc_b, FEAT, 512, 256, 8192);
    gemm_mma_kernel<0><<<dim3(384 / 64, 512 / 32), 256>>>(FEAT, gwih, gbih, GI, 512, 384, 256);

    // ---- GRU sequential scan ----
    {
        int smem = 64 * 384 * 4 + (384 + 128 + 128) * 4;
        cudaFuncSetAttribute(gru_scan_kernel, cudaFuncAttributeMaxDynamicSharedMemorySize, smem);
        gru_scan_kernel<<<8, 384, smem>>>(GI, done, grustate, gwhh, gbhh, HID);
    }

    // ---- actor / critic heads -> (512, 4) ----
    heads_kernel<<<512, 128>>>(HID, aw, ab, cw, cb, out);
}

// round 16
// speedup vs baseline: 1.3178x; 1.0318x over previous
#include <cuda_runtime.h>
#include <cuda_fp16.h>
#include <math.h>

// ---------------- scratch (device globals; no allocations) ----------------
__device__ float g_X[33554432];
__device__ float g_O[33554432];
__device__ float g_feat[512 * 256];
__device__ float g_gi[512 * 384];
__device__ float g_hid[512 * 128];
__device__ float g_fcwT[256 * 8192];
__device__ __half2 g_wperm2[49152];

__device__ __forceinline__ float sigf(float x) { return 1.0f / (1.0f + expf(-x)); }

__device__ __forceinline__ unsigned tf32u(float x) {
    unsigned r;
    asm("cvt.rna.tf32.f32 %0, %1;" : "=r"(r) : "f"(x));
    return r;
}
__device__ __forceinline__ float tf32f(float x) { return __uint_as_float(tf32u(x)); }

__device__ __forceinline__ void mma8(float* c, unsigned a0, unsigned a1, unsigned a2, unsigned a3,
                                     float b0f, float b1f) {
    unsigned b0 = __float_as_uint(b0f), b1 = __float_as_uint(b1f);
    asm volatile(
        "mma.sync.aligned.m16n8k8.row.col.f32.tf32.tf32.f32 "
        "{%0,%1,%2,%3},{%4,%5,%6,%7},{%8,%9},{%0,%1,%2,%3};"
        : "+f"(c[0]), "+f"(c[1]), "+f"(c[2]), "+f"(c[3])
        : "r"(a0), "r"(a1), "r"(a2), "r"(a3), "r"(b0), "r"(b1));
}
__device__ __forceinline__ void mma16h(float* c, unsigned a0, unsigned a1, unsigned a2, unsigned a3,
                                       unsigned b0, unsigned b1) {
    asm volatile(
        "mma.sync.aligned.m16n8k16.row.col.f32.f16.f16.f32 "
        "{%0,%1,%2,%3},{%4,%5,%6,%7},{%8,%9},{%0,%1,%2,%3};"
        : "+f"(c[0]), "+f"(c[1]), "+f"(c[2]), "+f"(c[3])
        : "r"(a0), "r"(a1), "r"(a2), "r"(a3), "r"(b0), "r"(b1));
}
__device__ __forceinline__ void mma8h(float* c, unsigned a0, unsigned a1, unsigned b0) {
    asm volatile(
        "mma.sync.aligned.m16n8k8.row.col.f32.f16.f16.f32 "
        "{%0,%1,%2,%3},{%4,%5},{%6},{%0,%1,%2,%3};"
        : "+f"(c[0]), "+f"(c[1]), "+f"(c[2]), "+f"(c[3])
        : "r"(a0), "r"(a1), "r"(b0));
}
__device__ __forceinline__ void ldsm_x4(unsigned& r0, unsigned& r1, unsigned& r2, unsigned& r3,
                                        unsigned addr) {
    asm volatile("ldmatrix.sync.aligned.m8n8.x4.shared.b16 {%0,%1,%2,%3}, [%4];"
                 : "=r"(r0), "=r"(r1), "=r"(r2), "=r"(r3) : "r"(addr));
}
__device__ __forceinline__ void ldsm_x2(unsigned& r0, unsigned& r1, unsigned addr) {
    asm volatile("ldmatrix.sync.aligned.m8n8.x2.shared.b16 {%0,%1}, [%2];"
                 : "=r"(r0), "=r"(r1) : "r"(addr));
}
#define U(x) __float_as_uint(x)

__device__ __forceinline__ int pslot(int p, int PAIRS) {
    if (PAIRS == 4)  return p;
    if (PAIRS == 8)  return 2 * (p & 3) + (p >> 2);
    return 4 * (p & 3) + (p >> 2);
}
__device__ __forceinline__ unsigned packh2(float a, float b) {
    __half2 h = __floats2half2_rn(a, b);
    return *(unsigned*)&h;
}
__device__ __forceinline__ unsigned relu_u(unsigned u) {
    __half2 h = *(__half2*)&u;
    h = __hmax2(h, __half2half2(__float2half(0.0f)));
    return *(unsigned*)&h;
}
__device__ __forceinline__ uint4 relu4(uint4 v) {
    v.x = relu_u(v.x); v.y = relu_u(v.y); v.z = relu_u(v.z); v.w = relu_u(v.w);
    return v;
}

// ---------------- weight permute prepass -> fp16 pairs [tap][co][pslot] ----
__global__ void wperm_all_kernel(const float* __restrict__ s0c, const float* __restrict__ s0r,
                                 const float* __restrict__ s1c, const float* __restrict__ s1r,
                                 const float* __restrict__ s2c, const float* __restrict__ s2r,
                                 __half2* __restrict__ dst) {
    int i = blockIdx.x * 256 + threadIdx.x;
    if (i >= 48960) return;
    const float* src; int CIN, PAIRS, COUT, base;
    if (i < 576)        { src = s0c; CIN = 6;  PAIRS = 4;  COUT = 16; base = 0; }
    else if (i < 5184)  { src = s0r; CIN = 16; PAIRS = 8;  COUT = 16; base = 576; }
    else if (i < 7488)  { src = s1c; CIN = 16; PAIRS = 8;  COUT = 32; base = 5184; }
    else if (i < 25920) { src = s1r; CIN = 32; PAIRS = 16; COUT = 32; base = 7488; }
    else if (i < 30528) { src = s2c; CIN = 32; PAIRS = 16; COUT = 32; base = 25920; }
    else                { src = s2r; CIN = 32; PAIRS = 16; COUT = 32; base = 30528; }
    int li = i - base;
    int tap = li % 9; int r = li / 9;
    int p = r % PAIRS; r /= PAIRS;
    int co = r % COUT; int cv = r / COUT;
    int ci0 = 2 * p, ci1 = 2 * p + 1;
    float v0 = (ci0 < CIN) ? src[((cv * COUT + co) * CIN + ci0) * 9 + tap] : 0.0f;
    float v1 = (ci1 < CIN) ? src[((cv * COUT + co) * CIN + ci1) * 9 + tap] : 0.0f;
    dst[base + cv * 9 * COUT * PAIRS + (tap * COUT + co) * PAIRS + pslot(p, PAIRS)] =
        __floats2half2_rn(v0, v1);
}

// permute fc_w[n][c*256+p] -> g_fcwT[n][p*32+c]
__global__ void fcw_permute(const float* __restrict__ w, float* __restrict__ wt) {
    int i = blockIdx.x * 256 + threadIdx.x;
    if (i >= 256 * 8192) return;
    int n = i >> 13;
    int r = i & 8191;
    int c = r >> 8, p = r & 255;
    wt[(n << 13) + p * 32 + c] = w[i];
}

// ---------------- fused conv kernel (TW = tile width, height 16) -----------
// MODE 0: conv -> maxpool -> fp16 out.  MODE 1: resblock fp16 out.  MODE 2: fp32 NHWC out.
template <int TW, int CIN, int COUT, bool RELU_IN, int MODE, bool RELU_OUT, bool NCHW, int MINB>
__global__ __launch_bounds__(256, MINB) void conv_fused_kernel(
    const void* __restrict__ in, const __half2* __restrict__ w1,
    const float* __restrict__ b1v, const __half2* __restrict__ w2,
    const float* __restrict__ b2v, void* __restrict__ out,
    const void* __restrict__ resid, int H, int W) {
    constexpr int CINP = (CIN <= 8) ? 8 : ((CIN <= 16) ? 16 : 32);
    constexpr int PAIRS = CINP / 2;
    constexpr int POP = COUT / 2;
    constexpr int NB = COUT / 8;
    constexpr int HW = TW + 4;
    constexpr int RW = TW + 2;
    constexpr int HPIX = 20 * HW;
    constexpr int NPIX = 18 * RW;
    constexpr int NSUB = (NPIX + 127) / 128;
    constexpr int ISTR = (PAIRS == 4) ? 4 : ((PAIRS == 8) ? 12 : 16);
    constexpr int IN_W = HPIX * ISTR;
    constexpr int MSTR = (MODE == 0) ? POP : ((POP == 8) ? 12 : 16);
    constexpr int MID_W = NPIX * MSTR;

    extern __shared__ __half2 smh[];
    __half2* s_in2 = smh;
    __half2* s_mid2 = smh + IN_W;

    const int tid = threadIdx.x;
    const int n = blockIdx.z;
    const int by = blockIdx.y * 16, bx = blockIdx.x * TW;
    const unsigned sb_in = (unsigned)__cvta_generic_to_shared(s_in2);
    const unsigned sb_mid = (unsigned)__cvta_generic_to_shared(s_mid2);

    // zero mid only for edge tiles (interior tiles fully overwrite the read range),
    // using STS.128 over the consumed byte range only.
    const bool edge = (by == 0) | (by + 16 >= H) | (bx == 0) | (bx + TW >= W);
    if (edge) {
        uint4 z = make_uint4(0u, 0u, 0u, 0u);
        if (MODE != 0 && POP == 8) {
            // stride 12 words (48B); consumed bytes 0..31 -> two uint4 per pixel
            for (int p = tid; p < NPIX; p += 256) {
                *(uint4*)(s_mid2 + p * 12) = z;
                *(uint4*)(s_mid2 + p * 12 + 4) = z;
            }
        } else {
            for (int i = tid; i < MID_W / 4; i += 256) ((uint4*)s_mid2)[i] = z;
        }
    }

    // ---- stage halo (20 x HW) ----
    for (int p = tid; p < HPIX; p += 256) {
        int iy = p / HW, ix = p - iy * HW;
        int gy = by + iy - 2, gx = bx + ix - 2;
        bool ok = (gy >= 0 && gy < H && gx >= 0 && gx < W);
        if (NCHW) {
            const float* inf = (const float*)in;
            uint4 wv = make_uint4(0u, 0u, 0u, 0u);
            if (ok) {
                long base = ((long)n * CIN * H + gy) * W + gx;
                long st = (long)H * W;
                wv = make_uint4(packh2(inf[base], inf[base + st]),
                                packh2(inf[base + 2 * st], inf[base + 3 * st]),
                                packh2(inf[base + 4 * st], inf[base + 5 * st]), 0u);
            }
            *(uint4*)(s_in2 + p * 4) = wv;
        } else if (PAIRS == 8) {
            uint4 lo = make_uint4(0u, 0u, 0u, 0u), hi = lo;
            if (ok) {
                const uint4* gp = (const uint4*)((const __half2*)in + ((long)(n * H + gy) * W + gx) * 8);
                lo = gp[0]; hi = gp[1];
                if (RELU_IN) { lo = relu4(lo); hi = relu4(hi); }
            }
            *(uint4*)(s_in2 + p * 12) = lo;
            *(uint4*)(s_in2 + p * 12 + 4) = hi;
        } else {
            uint4 v0 = make_uint4(0,0,0,0), v1 = v0, v2 = v0, v3 = v0;
            if (ok) {
                const uint4* gp = (const uint4*)((const __half2*)in + ((long)(n * H + gy) * W + gx) * 16);
                v0 = gp[0]; v1 = gp[1]; v2 = gp[2]; v3 = gp[3];
                if (RELU_IN) { v0 = relu4(v0); v1 = relu4(v1); v2 = relu4(v2); v3 = relu4(v3); }
            }
            *(uint4*)(s_in2 + p * 16) = v0;
            *(uint4*)(s_in2 + p * 16 + 4) = v1;
            *(uint4*)(s_in2 + p * 16 + 8) = v2;
            *(uint4*)(s_in2 + p * 16 + 12) = v3;
        }
    }
    __syncthreads();

    const int warp = tid >> 5, lane = tid & 31, g = lane >> 2, t = lane & 3;
    const char* suc = (const char*)s_in2;
    const char* w1c = (const char*)w1;

    float acc1[NSUB][NB][4];
#pragma unroll
    for (int s = 0; s < NSUB; s++)
#pragma unroll
        for (int nb = 0; nb < NB; nb++)
#pragma unroll
            for (int q = 0; q < 4; q++) acc1[s][nb][q] = 0.0f;

    unsigned lmaddr[NSUB];
    const char* a0p[NSUB]; const char* a1p[NSUB];
    if (PAIRS == 4 || PAIRS == 8) {
        int i8 = lane & 7, mm = lane >> 3;
#pragma unroll
        for (int s = 0; s < NSUB; s++) {
            int tt = warp + 8 * s;
            int p = tt * 16 + i8 + (mm & 1) * 8;
            if (p > NPIX - 1) p = NPIX - 1;
            int pix = (p / RW + 1) * HW + (p % RW) + 1;
            if (PAIRS == 4) lmaddr[s] = sb_in + pix * 16;
            else            lmaddr[s] = sb_in + pix * 48 + (mm >> 1) * 16;
        }
    } else {
#pragma unroll
        for (int s = 0; s < NSUB; s++) {
            int tt = warp + 8 * s;
            int p0 = tt * 16 + g, p1 = p0 + 8;
            int q0 = p0 > NPIX - 1 ? NPIX - 1 : p0, q1 = p1 > NPIX - 1 ? NPIX - 1 : p1;
            int b0 = (q0 / RW + 1) * HW + (q0 % RW + 1);
            int b1 = (q1 / RW + 1) * HW + (q1 % RW + 1);
            a0p[s] = suc + b0 * 64 + t * 16;
            a1p[s] = suc + b1 * 64 + t * 16;
        }
    }
    const char* wp1[NB];
#pragma unroll
    for (int nb = 0; nb < NB; nb++) {
        int co = nb * 8 + g;
        if (PAIRS == 4)      wp1[nb] = w1c + co * 16 + t * 4;
        else if (PAIRS == 8) wp1[nb] = w1c + co * 32 + t * 8;
        else                 wp1[nb] = w1c + co * 64 + t * 16;
    }

#pragma unroll
    for (int tap = 0; tap < 9; tap++) {
        const int dy = tap / 3 - 1, dx = tap % 3 - 1;
        const int off = dy * HW + dx;
        if (PAIRS == 4) {
            const int wimm = tap * COUT * 16;
            unsigned vb[NB];
#pragma unroll
            for (int nb = 0; nb < NB; nb++) vb[nb] = *(const unsigned*)(wp1[nb] + wimm);
#pragma unroll
            for (int s = 0; s < NSUB; s++) {
                unsigned a0, a1;
                ldsm_x2(a0, a1, lmaddr[s] + off * 16);
#pragma unroll
                for (int nb = 0; nb < NB; nb++) mma8h(acc1[s][nb], a0, a1, vb[nb]);
            }
        } else if (PAIRS == 8) {
            const int wimm = tap * COUT * 32;
            uint2 vb[NB];
#pragma unroll
            for (int nb = 0; nb < NB; nb++) vb[nb] = *(const uint2*)(wp1[nb] + wimm);
#pragma unroll
            for (int s = 0; s < NSUB; s++) {
                unsigned a0, a1, a2, a3;
                ldsm_x4(a0, a1, a2, a3, lmaddr[s] + off * 48);
#pragma unroll
                for (int nb = 0; nb < NB; nb++)
                    mma16h(acc1[s][nb], a0, a1, a2, a3, vb[nb].x, vb[nb].y);
            }
        } else {
            const int wimm = tap * COUT * 64, aimm = off * 64;
            uint4 vb[NB];
#pragma unroll
            for (int nb = 0; nb < NB; nb++) vb[nb] = *(const uint4*)(wp1[nb] + wimm);
#pragma unroll
            for (int s = 0; s < NSUB; s++) {
                uint4 va0 = *(const uint4*)(a0p[s] + aimm);
                uint4 va1 = *(const uint4*)(a1p[s] + aimm);
#pragma unroll
                for (int nb = 0; nb < NB; nb++) {
                    mma16h(acc1[s][nb], va0.x, va1.x, va0.y, va1.y, vb[nb].x, vb[nb].y);
                    mma16h(acc1[s][nb], va0.z, va1.z, va0.w, va1.w, vb[nb].z, vb[nb].w);
                }
            }
        }
    }

    // ---- store conv1 results to mid ----
#pragma unroll
    for (int s = 0; s < NSUB; s++) {
        int pbase = (warp + 8 * s) * 16 + g;
#pragma unroll
        for (int half = 0; half < 2; half++) {
            int p = pbase + 8 * half;
            if (p < NPIX) {
                int r = p / RW, c = p - r * RW;
                int gy = by - 1 + r, gx = bx - 1 + c;
                if (gy >= 0 && gy < H && gx >= 0 && gx < W) {
#pragma unroll
                    for (int nb = 0; nb < NB; nb++) {
                        int co = nb * 8 + 2 * t;
                        int pr = nb * 4 + t;
                        float v0 = acc1[s][nb][2 * half + 0] + b1v[co];
                        float v1 = acc1[s][nb][2 * half + 1] + b1v[co + 1];
                        if (MODE == 0) {
                            s_mid2[p * POP + pr] = __floats2half2_rn(v0, v1);
                        } else if (POP == 8) {
                            s_mid2[p * 12 + pr] =
                                __floats2half2_rn(fmaxf(v0, 0.0f), fmaxf(v1, 0.0f));
                        } else {
                            s_mid2[p * 16 + (pslot(pr, 16) ^ ((p & 1) << 3))] =
                                __floats2half2_rn(fmaxf(v0, 0.0f), fmaxf(v1, 0.0f));
                        }
                    }
                }
            }
        }
    }
    __syncthreads();

    if (MODE == 0) {
        int H2 = H >> 1, W2 = W >> 1;
        __half2* outh = (__half2*)out;
        for (int o = tid; o < 4 * TW * POP; o += 256) {
            int pr = o % POP; int pp = o / POP;
            int ly = pp / (TW / 2), lx = pp % (TW / 2);
            __half2 m = __floats2half2_rn(-65504.0f, -65504.0f);
#pragma unroll
            for (int dy = 0; dy < 3; dy++) {
                int r = 2 * ly + dy;
                int gy = by - 1 + r;
                if (gy < 0 || gy >= H) continue;
#pragma unroll
                for (int dxx = 0; dxx < 3; dxx++) {
                    int c = 2 * lx + dxx;
                    int gx = bx - 1 + c;
                    if (gx < 0 || gx >= W) continue;
                    m = __hmax2(m, s_mid2[(r * RW + c) * POP + pr]);
                }
            }
            long op = ((long)n * H2 + (by / 2 + ly)) * W2 + (bx / 2 + lx);
            outh[op * POP + (COUT == 16 ? pr : pslot(pr, 16))] = m;
        }
    } else {
        const char* muc = (const char*)s_mid2;
        const char* w2c = (const char*)w2;
        const int wr0 = warp * 2;
        float acc[2][NB][4];
#pragma unroll
        for (int r = 0; r < 2; r++)
#pragma unroll
            for (int nb = 0; nb < NB; nb++)
#pragma unroll
                for (int q = 0; q < 4; q++) acc[r][nb][q] = 0.0f;

        unsigned m_lm[2];
        if (POP == 8) {
            int i8 = lane & 7, mm = lane >> 3;
#pragma unroll
            for (int r = 0; r < 2; r++) {
                int pix = (wr0 + r + 1) * RW + 1 + i8 + (mm & 1) * 8;
                m_lm[r] = sb_mid + pix * 48 + (mm >> 1) * 16;
            }
        }
        const char* wp2[NB];
#pragma unroll
        for (int nb = 0; nb < NB; nb++) {
            int co = nb * 8 + g;
            wp2[nb] = (POP == 8) ? (w2c + co * 32 + t * 8) : (w2c + co * 64 + t * 16);
        }

#pragma unroll
        for (int tap = 0; tap < 9; tap++) {
            const int dy = tap / 3 - 1, dx = tap % 3 - 1;
            const int off = dy * RW + dx;
            if (POP == 8) {
                const int wimm = tap * COUT * 32;
                uint2 vb[NB];
#pragma unroll
                for (int nb = 0; nb < NB; nb++) vb[nb] = *(const uint2*)(wp2[nb] + wimm);
#pragma unroll
                for (int r = 0; r < 2; r++) {
                    unsigned a0, a1, a2, a3;
                    ldsm_x4(a0, a1, a2, a3, m_lm[r] + off * 48);
#pragma unroll
                    for (int nb = 0; nb < NB; nb++)
                        mma16h(acc[r][nb], a0, a1, a2, a3, vb[nb].x, vb[nb].y);
                }
            } else {
                const int wimm = tap * COUT * 64;
                uint4 vb[NB];
#pragma unroll
                for (int nb = 0; nb < NB; nb++) vb[nb] = *(const uint4*)(wp2[nb] + wimm);
#pragma unroll
                for (int r = 0; r < 2; r++) {
                    int pb0 = (wr0 + r + dy + 1) * RW + dx + 1 + g;
                    int pb1 = pb0 + 8;
                    const char* q0 = muc + pb0 * 64 + (t * 16 ^ ((pb0 & 1) << 5));
                    const char* q1 = muc + pb1 * 64 + (t * 16 ^ ((pb1 & 1) << 5));
                    uint4 va0 = *(const uint4*)q0;
                    uint4 va1 = *(const uint4*)q1;
#pragma unroll
                    for (int nb = 0; nb < NB; nb++) {
                        mma16h(acc[r][nb], va0.x, va1.x, va0.y, va1.y, vb[nb].x, vb[nb].y);
                        mma16h(acc[r][nb], va0.z, va1.z, va0.w, va1.w, vb[nb].z, vb[nb].w);
                    }
                }
            }
        }

        const __half2* res2 = (const __half2*)resid;
#pragma unroll
        for (int r = 0; r < 2; r++) {
            int oy = by + wr0 + r;
            long oprow = (long)(n * H + oy) * W + bx;
#pragma unroll
            for (int nb = 0; nb < NB; nb++) {
                int pr = nb * 4 + t;
                int sl = (POP == 8) ? pr : pslot(pr, 16);
                int co = 2 * pr;
                float bv0 = b2v[co], bv1 = b2v[co + 1];
                long i0 = (oprow + g) * POP + sl;
                long i1 = (oprow + g + 8) * POP + sl;
                float2 r0 = __half22float2(res2[i0]);
                float2 r1 = __half22float2(res2[i1]);
                float v00 = acc[r][nb][0] + bv0 + r0.x, v01 = acc[r][nb][1] + bv1 + r0.y;
                float v10 = acc[r][nb][2] + bv0 + r1.x, v11 = acc[r][nb][3] + bv1 + r1.y;
                if (RELU_OUT) {
                    v00 = fmaxf(v00, 0.0f); v01 = fmaxf(v01, 0.0f);
                    v10 = fmaxf(v10, 0.0f); v11 = fmaxf(v11, 0.0f);
                }
                if (MODE == 1) {
                    __half2* outh = (__half2*)out;
                    outh[i0] = __floats2half2_rn(v00, v01);
                    outh[i1] = __floats2half2_rn(v10, v11);
                } else {
                    float* outf = (float*)out;
                    *(float2*)(outf + (oprow + g) * COUT + co) = make_float2(v00, v01);
                    *(float2*)(outf + (oprow + g + 8) * COUT + co) = make_float2(v10, v11);
                }
            }
        }
    }
}

// ---------------- fused CBAM (fp32 NHWC X, in place) ----------------
__global__ __launch_bounds__(256) void cbam_fused_kernel(
    float* __restrict__ x, const float* __restrict__ fc1, const float* __restrict__ fc2,
    const float* __restrict__ spw) {
    __shared__ float s_x[256 * 36];
    __shared__ float rs[8][32], rm[8][32];
    __shared__ float s_mean[32], s_max[32], s_h[8], s_ca[32], s_sp[512], s_w[98];
    const int n = blockIdx.x, tid = threadIdx.x;

    float* gbase = x + ((long)n * 256 + tid) * 32;
#pragma unroll
    for (int c = 0; c < 32; c += 4)
        *(float4*)(s_x + tid * 36 + c) = *(const float4*)(gbase + c);
    if (tid < 98) s_w[tid] = spw[tid];
    __syncthreads();

    {
        int g = tid >> 5, c = tid & 31;
        float sm = 0.0f, mx = -3.4e38f;
        for (int p = g; p < 256; p += 8) {
            float v = s_x[p * 36 + c];
            sm += v; mx = fmaxf(mx, v);
        }
        rs[g][c] = sm; rm[g][c] = mx;
    }
    __syncthreads();
    if (tid < 32) {
        float s = 0.0f, m = -3.4e38f;
        for (int q = 0; q < 8; q++) { s += rs[q][tid]; m = fmaxf(m, rm[q][tid]); }
        s_mean[tid] = s * (1.0f / 256.0f); s_max[tid] = m;
    }
    __syncthreads();
    if (tid < 8) {
        float hm = 0.0f, hx = 0.0f;
        for (int k = 0; k < 32; k++) {
            float wv = fc1[tid * 32 + k];
            hm += s_mean[k] * wv; hx += s_max[k] * wv;
        }
        s_h[tid] = fmaxf(hm, 0.0f) + fmaxf(hx, 0.0f);
    }
    __syncthreads();
    if (tid < 32) {
        float o = 0.0f;
        for (int j = 0; j < 8; j++) o += s_h[j] * fc2[tid * 8 + j];
        s_ca[tid] = sigf(o);
    }
    __syncthreads();

    {
        float sum = 0.0f, mx = -3.4e38f;
#pragma unroll
        for (int c = 0; c < 32; c++) {
            float v = s_x[tid * 36 + c] * s_ca[c];
            s_x[tid * 36 + c] = v;
            sum += v; mx = fmaxf(mx, v);
        }
        s_sp[tid] = sum * (1.0f / 32.0f);
        s_sp[256 + tid] = mx;
    }
    __syncthreads();

    {
        int oy = tid >> 4, ox = tid & 15;
        float a = 0.0f;
#pragma unroll
        for (int ci = 0; ci < 2; ci++)
            for (int ky = 0; ky < 7; ky++) {
                int y = oy + ky - 3;
                if (y < 0 || y >= 16) continue;
                for (int kx = 0; kx < 7; kx++) {
                    int xx = ox + kx - 3;
                    if (xx < 0 || xx >= 16) continue;
                    a = fmaf(s_sp[ci * 256 + y * 16 + xx], s_w[(ci * 7 + ky) * 7 + kx], a);
                }
            }
        float sa = sigf(a);
#pragma unroll
        for (int c = 0; c < 32; c += 4) {
            float4 v;
            v.x = s_x[tid * 36 + c] * sa;
            v.y = s_x[tid * 36 + c + 1] * sa;
            v.z = s_x[tid * 36 + c + 2] * sa;
            v.w = s_x[tid * 36 + c + 3] * sa;
            *(float4*)(gbase + c) = v;
        }
    }
}

// ---------------- tf32 MMA GEMM, single-sync double-buffered --------------
// NT: 1 -> block 32x32 (8 warps 2x4, warp m16n8); 2 -> block 32x64 (warp m16n16)
template <int RELU, int NT>
__global__ __launch_bounds__(256) void gemm_mma_kernel(
    const float* __restrict__ A, const float* __restrict__ B,
    const float* __restrict__ bias, float* __restrict__ C,
    int M, int N, int K) {
    constexpr int BN = 32 * NT;
    __shared__ float sA[2][32 * 36], sB[2][BN * 36];
    const int tid = threadIdx.x;
    const int bm = blockIdx.y * 32, bn = blockIdx.x * BN;
    const int warp = tid >> 5, lane = tid & 31, g = lane >> 2, t = lane & 3;
    const int wm = warp >> 2, wn = warp & 3;
    const int lrA = tid >> 3, lcA = (tid & 7) * 4;
    const int lrB = (NT == 2) ? (tid >> 2) : (tid >> 3);
    const int lcB = (NT == 2) ? ((tid & 3) * 8) : ((tid & 7) * 4);

    float acc[NT][4];
#pragma unroll
    for (int i = 0; i < NT; i++)
#pragma unroll
        for (int q = 0; q < 4; q++) acc[i][q] = 0.0f;

    const float* pA = A + (long)(bm + lrA) * K + lcA;
    const float* pB = B + (long)(bn + lrB) * K + lcB;

    float4 va = *(const float4*)(pA);
    float4 vb0 = *(const float4*)(pB);
    float4 vb1;
    if (NT == 2) vb1 = *(const float4*)(pB + 4);
    {
        float* pa = sA[0] + lrA * 36 + lcA;
        float* pb = sB[0] + lrB * 36 + lcB;
        pa[0]=tf32f(va.x); pa[1]=tf32f(va.y); pa[2]=tf32f(va.z); pa[3]=tf32f(va.w);
        pb[0]=tf32f(vb0.x); pb[1]=tf32f(vb0.y); pb[2]=tf32f(vb0.z); pb[3]=tf32f(vb0.w);
        if (NT == 2) {
            pb[4]=tf32f(vb1.x); pb[5]=tf32f(vb1.y); pb[6]=tf32f(vb1.z); pb[7]=tf32f(vb1.w);
        }
    }
    __syncthreads();

    int buf = 0;
    for (int k0 = 0; k0 < K; k0 += 32) {
        bool has_next = (k0 + 32 < K);
        if (has_next) {
            va = *(const float4*)(pA + k0 + 32);
            vb0 = *(const float4*)(pB + k0 + 32);
            if (NT == 2) vb1 = *(const float4*)(pB + k0 + 36);
        }
        const float* cA = sA[buf];
        const float* cB = sB[buf];
#pragma unroll
        for (int ks = 0; ks < 4; ks++) {
            const int k = ks * 8;
            const int r0 = wm * 16 + g;
            unsigned a0 = U(cA[r0 * 36 + k + t]),     a1 = U(cA[(r0 + 8) * 36 + k + t]);
            unsigned a2 = U(cA[r0 * 36 + k + t + 4]), a3 = U(cA[(r0 + 8) * 36 + k + t + 4]);
#pragma unroll
            for (int nt = 0; nt < NT; nt++) {
                int nr = wn * (8 * NT) + nt * 8 + g;
                mma8(acc[nt], a0, a1, a2, a3, cB[nr * 36 + k + t], cB[nr * 36 + k + t + 4]);
            }
        }
        if (has_next) {
            float* pa = sA[buf ^ 1] + lrA * 36 + lcA;
            float* pb = sB[buf ^ 1] + lrB * 36 + lcB;
            pa[0]=tf32f(va.x); pa[1]=tf32f(va.y); pa[2]=tf32f(va.z); pa[3]=tf32f(va.w);
            pb[0]=tf32f(vb0.x); pb[1]=tf32f(vb0.y); pb[2]=tf32f(vb0.z); pb[3]=tf32f(vb0.w);
            if (NT == 2) {
                pb[4]=tf32f(vb1.x); pb[5]=tf32f(vb1.y); pb[6]=tf32f(vb1.z); pb[7]=tf32f(vb1.w);
            }
        }
        __syncthreads();
        buf ^= 1;
    }
#pragma unroll
    for (int nt = 0; nt < NT; nt++) {
        int n0 = bn + wn * (8 * NT) + nt * 8 + 2 * t;
        int m0 = bm + wm * 16 + g;
        float b0 = bias[n0], b1 = bias[n0 + 1];
        float v00 = acc[nt][0] + b0, v01 = acc[nt][1] + b1;
        float v10 = acc[nt][2] + b0, v11 = acc[nt][3] + b1;
        if (RELU) {
            v00 = fmaxf(v00, 0.0f); v01 = fmaxf(v01, 0.0f);
            v10 = fmaxf(v10, 0.0f); v11 = fmaxf(v11, 0.0f);
        }
        C[(long)m0 * N + n0] = v00;       C[(long)m0 * N + n0 + 1] = v01;
        C[(long)(m0 + 8) * N + n0] = v10; C[(long)(m0 + 8) * N + n0 + 1] = v11;
    }
}

// ---------------- GRU scan (whh as fp16 pairs in smem) ----------------
__global__ void gru_scan_kernel(const float* __restrict__ gi, const float* __restrict__ done,
                                const float* __restrict__ h0, const float* __restrict__ whh,
                                const float* __restrict__ bhh, float* __restrict__ hidden) {
    extern __shared__ __half2 smg[];
    __half2* s_whh = smg;
    float* s_gh = (float*)(smg + 64 * 384);
    float* s_h = s_gh + 384;
    float* s_hm = s_h + 128;
    int b = blockIdx.x, j = threadIdx.x;

    for (int i = j; i < 64 * 384; i += 384) {
        int jj = i / 64, k2 = i - jj * 64;
        s_whh[k2 * 384 + jj] = __floats2half2_rn(whh[jj * 128 + 2 * k2],
                                                 whh[jj * 128 + 2 * k2 + 1]);
    }
    if (j < 128) s_h[j] = h0[b * 128 + j];
    __syncthreads();

    float bh = bhh[j];
    for (int t = 0; t < 64; t++) {
        float dt = done[t * 8 + b];
        if (j < 128) s_hm[j] = (1.0f - dt) * s_h[j];
        __syncthreads();
        float acc = bh;
#pragma unroll 8
        for (int k2 = 0; k2 < 64; k2++) {
            float2 wv = __half22float2(s_whh[k2 * 384 + j]);
            float2 hm = *(const float2*)(s_hm + 2 * k2);
            acc = fmaf(hm.x, wv.x, acc);
            acc = fmaf(hm.y, wv.y, acc);
        }
        s_gh[j] = acc;
        __syncthreads();
        if (j < 128) {
            const float* gr = gi + (long)(t * 8 + b) * 384;
            float r = sigf(gr[j] + s_gh[j]);
            float z = sigf(gr[128 + j] + s_gh[128 + j]);
            float nn = tanhf(gr[256 + j] + r * s_gh[256 + j]);
            float hn = (1.0f - z) * nn + z * s_hm[j];
            s_h[j] = hn;
            hidden[(long)(t * 8 + b) * 128 + j] = hn;
        }
        __syncthreads();
    }
}

// ---------------- actor/critic heads ----------------
__global__ void heads_kernel(const float* __restrict__ hidden, const float* __restrict__ aw,
                             const float* __restrict__ ab, const float* __restrict__ cw,
                             const float* __restrict__ cb, float* __restrict__ out) {
    int row = blockIdx.x, t = threadIdx.x;
    __shared__ float s_h[128];
    s_h[t] = hidden[(long)row * 128 + t];
    __syncthreads();
    if (t < 4) {
        const float* w = (t < 3) ? (aw + t * 128) : cw;
        float s = (t < 3) ? ab[t] : cb[0];
        for (int k = 0; k < 128; k++) s = fmaf(s_h[k], w[k], s);
        out[row * 4 + t] = s;
    }
}

// ---------------- host-side launch helpers ----------------
template <int TW, int CIN, int COUT, bool RELU_IN, int MODE, bool RELU_OUT, bool NCHW, int MINB>
static void launch_fused(const void* in, const __half2* w1, const float* b1,
                         const __half2* w2, const float* b2,
                         void* out, const void* resid, int H, int W) {
    constexpr int CINP = (CIN <= 8) ? 8 : ((CIN <= 16) ? 16 : 32);
    constexpr int PAIRS = CINP / 2;
    constexpr int POP = COUT / 2;
    constexpr int ISTR = (PAIRS == 4) ? 4 : ((PAIRS == 8) ? 12 : 16);
    constexpr int MSTR = (MODE == 0) ? POP : ((POP == 8) ? 12 : 16);
    int smem = (20 * (TW + 4) * ISTR + 18 * (TW + 2) * MSTR) * 4;
    auto kfn = conv_fused_kernel<TW, CIN, COUT, RELU_IN, MODE, RELU_OUT, NCHW, MINB>;
    cudaFuncSetAttribute(kfn, cudaFuncAttributeMaxDynamicSharedMemorySize, smem);
    dim3 grid(W / TW, H / 16, 512);
    kfn<<<grid, 256, smem>>>(in, w1, b1, w2, b2, out, resid, H, W);
}

extern "C" void kernel_launch(void* const* d_in, const int* in_sizes, int n_in,
                              void* d_out, int out_size) {
    (void)in_sizes; (void)n_in; (void)out_size;
    const float* x        = (const float*)d_in[0];
    const float* done     = (const float*)d_in[1];
    const float* grustate = (const float*)d_in[2];
    const float* s0_cw = (const float*)d_in[3];
    const float* s0_cb = (const float*)d_in[4];
    const float* s0_rw = (const float*)d_in[5];
    const float* s0_rb = (const float*)d_in[6];
    const float* s1_cw = (const float*)d_in[7];
    const float* s1_cb = (const float*)d_in[8];
    const float* s1_rw = (const float*)d_in[9];
    const float* s1_rb = (const float*)d_in[10];
    const float* s2_cw = (const float*)d_in[11];
    const float* s2_cb = (const float*)d_in[12];
    const float* s2_rw = (const float*)d_in[13];
    const float* s2_rb = (const float*)d_in[14];
    const float* cbam_fc1 = (const float*)d_in[15];
    const float* cbam_fc2 = (const float*)d_in[16];
    const float* cbam_spw = (const float*)d_in[17];
    const float* fc_w  = (const float*)d_in[18];
    const float* fc_b  = (const float*)d_in[19];
    const float* gwih  = (const float*)d_in[20];
    const float* gwhh  = (const float*)d_in[21];
    const float* gbih  = (const float*)d_in[22];
    const float* gbhh  = (const float*)d_in[23];
    const float* aw    = (const float*)d_in[24];
    const float* ab    = (const float*)d_in[25];
    const float* cw    = (const float*)d_in[26];
    const float* cb    = (const float*)d_in[27];
    float* out = (float*)d_out;

    float *X, *O, *FEAT, *GI, *HID, *FCWT;
    __half2* WP;
    cudaGetSymbolAddress((void**)&X, g_X);
    cudaGetSymbolAddress((void**)&O, g_O);
    cudaGetSymbolAddress((void**)&FEAT, g_feat);
    cudaGetSymbolAddress((void**)&GI, g_gi);
    cudaGetSymbolAddress((void**)&HID, g_hid);
    cudaGetSymbolAddress((void**)&FCWT, g_fcwT);
    cudaGetSymbolAddress((void**)&WP, g_wperm2);
    void *Xh = (void*)X, *Oh = (void*)O;

    const int OFF_S0C = 0;
    const int OFF_S0R = 576;
    const int OFF_S1C = 5184;
    const int OFF_S1R = 7488;
    const int OFF_S2C = 25920;
    const int OFF_S2R = 30528;

    wperm_all_kernel<<<(48960 + 255) / 256, 256>>>(s0_cw, s0_rw, s1_cw, s1_rw, s2_cw, s2_rw, WP);
    fcw_permute<<<(256 * 8192 + 255) / 256, 256>>>(fc_w, FCWT);

    // ---- stage 0: head TW32 MINB3; res TW16 MINB4 ----
    launch_fused<32, 6, 16, false, 0, false, true, 3>(x, WP + OFF_S0C, s0_cb, WP + OFF_S0C, s0_cb, Xh, nullptr, 128, 128);
    launch_fused<16, 16, 16, true, 1, false, false, 4>(Xh, WP + OFF_S0R + 0 * 1152, s0_rb + 0,
                                                       WP + OFF_S0R + 1 * 1152, s0_rb + 16, Oh, Xh, 64, 64);
    launch_fused<16, 16, 16, true, 1, false, false, 4>(Oh, WP + OFF_S0R + 2 * 1152, s0_rb + 32,
                                                       WP + OFF_S0R + 3 * 1152, s0_rb + 48, Xh, Oh, 64, 64);

    // ---- stage 1 ----
    launch_fused<16, 16, 32, false, 0, false, false, 3>(Xh, WP + OFF_S1C, s1_cb, WP + OFF_S1C, s1_cb, Oh, nullptr, 64, 64);
    launch_fused<16, 32, 32, true, 1, false, false, 3>(Oh, WP + OFF_S1R + 0 * 4608, s1_rb + 0,
                                                       WP + OFF_S1R + 1 * 4608, s1_rb + 32, Xh, Oh, 32, 32);
    launch_fused<16, 32, 32, true, 1, false, false, 3>(Xh, WP + OFF_S1R + 2 * 4608, s1_rb + 64,
                                                       WP + OFF_S1R + 3 * 4608, s1_rb + 96, Oh, Xh, 32, 32);

    // ---- stage 2 (final res writes fp32 NHWC + relu into X) ----
    launch_fused<16, 32, 32, false, 0, false, false, 3>(Oh, WP + OFF_S2C, s2_cb, WP + OFF_S2C, s2_cb, Xh, nullptr, 32, 32);
    launch_fused<16, 32, 32, true, 1, false, false, 3>(Xh, WP + OFF_S2R + 0 * 4608, s2_rb + 0,
                                                       WP + OFF_S2R + 1 * 4608, s2_rb + 32, Oh, Xh, 16, 16);
    launch_fused<16, 32, 32, true, 2, true, false, 3>(Oh, WP + OFF_S2R + 2 * 4608, s2_rb + 64,
                                                      WP + OFF_S2R + 3 * 4608, s2_rb + 96, (void*)X, Oh, 16, 16);

    // ---- fused CBAM (in place on fp32 X) ----
    cbam_fused_kernel<<<512, 256>>>(X, cbam_fc1, cbam_fc2, cbam_spw);

    // ---- FC (NT1: 128 blocks) + GRU input-gate GEMM (NT1: 192 blocks) ----
    gemm_mma_kernel<1, 1><<<dim3(256 / 32, 512 / 32), 256>>>(X, FCWT, fc_b, FEAT, 512, 256, 8192);
    gemm_mma_kernel<0, 1><<<dim3(384 / 32, 512 / 32), 256>>>(FEAT, gwih, gbih, GI, 512, 384, 256);

    // ---- GRU sequential scan ----
    {
        int smem = 64 * 384 * 4 + (384 + 128 + 128) * 4;
        cudaFuncSetAttribute(gru_scan_kernel, cudaFuncAttributeMaxDynamicSharedMemorySize, smem);
        gru_scan_kernel<<<8, 384, smem>>>(GI, done, grustate, gwhh, gbhh, HID);
    }

    // ---- actor / critic heads -> (512, 4) ----
    heads_kernel<<<512, 128>>>(HID, aw, ab, cw, cb, out);
}